// round 10
// baseline (speedup 1.0000x reference)
#include <cuda_runtime.h>
#include <cuda_fp16.h>
#include <cstdint>

#define N_NODES 50000
#define N_EDGES 800000
#define ET (N_EDGES + N_NODES)
#define FDIM 128
#define HEADS 4
#define N_GRAPHS 64
#define OUT_CH 10
#define NEG 0.2f

#define GEMM_BLOCKS ((N_NODES + 127) / 128)        // 391
#define SCAN_BLOCKS ((N_NODES + 1023) / 1024)      // 49

#define AS_STRIDE 68
#define BS_STRIDE 136
#define AS_WORDS (128 * AS_STRIDE)
#define SMEM_WORDS (AS_WORDS + 64 * BS_STRIDE)
#define SMEM_BYTES ((SMEM_WORDS + 256) * 4)

// ---------------- scratch ----------------
__device__ __half2 g_h16[(size_t)N_NODES * FDIM / 2];   // h in fp16 (gather source)
__device__ float g_buf[(size_t)N_NODES * FDIM];
__device__ float g_asrc[N_NODES * HEADS];
__device__ float g_adst[N_NODES * HEADS];
__device__ int   g_counts[N_NODES];
__device__ int   g_off[N_NODES + 1];
__device__ int   g_cur[N_NODES];
__device__ int   g_csrc[ET];
__device__ int   g_bsum[64];
__device__ int   g_bbase[64];

__device__ __forceinline__ float lrelu(float x) { return x > 0.f ? x : NEG * x; }
__device__ __forceinline__ uint32_t f2tf32(float f) {
    uint32_t r;
    asm("cvt.rna.tf32.f32 %0, %1;" : "=r"(r) : "f"(f));
    return r;
}
__device__ __forceinline__ void mma16n8k8(float* d, const uint32_t* a, uint32_t b0, uint32_t b1) {
    asm volatile(
        "mma.sync.aligned.m16n8k8.row.col.f32.tf32.tf32.f32 "
        "{%0,%1,%2,%3}, {%4,%5,%6,%7}, {%8,%9}, {%0,%1,%2,%3};"
        : "+f"(d[0]), "+f"(d[1]), "+f"(d[2]), "+f"(d[3])
        : "r"(a[0]), "r"(a[1]), "r"(a[2]), "r"(a[3]), "r"(b0), "r"(b1));
}

// ---------------- init counts to 1 (self loops pre-counted) ----------------
__global__ void k_init_counts() {
    int i = blockIdx.x * blockDim.x + threadIdx.x;
    if (i < N_NODES) g_counts[i] = 1;
}

// ---------------- degree histogram (vectorized over dst half) ----------------
__global__ void k_hist(const int* __restrict__ ei) {
    const int4* dst4 = (const int4*)(ei + N_EDGES);
    for (int i = blockIdx.x * blockDim.x + threadIdx.x; i < N_EDGES / 4; i += gridDim.x * blockDim.x) {
        int4 d = dst4[i];
        atomicAdd(&g_counts[d.x], 1);
        atomicAdd(&g_counts[d.y], 1);
        atomicAdd(&g_counts[d.z], 1);
        atomicAdd(&g_counts[d.w], 1);
    }
}

// ---------------- parallel 3-phase scan ----------------
__global__ void __launch_bounds__(1024) k_scan1() {
    __shared__ int sh[1024];
    int tid = threadIdx.x;
    int i = blockIdx.x * 1024 + tid;
    int v = (i < N_NODES) ? g_counts[i] : 0;
    sh[tid] = v;
    __syncthreads();
#pragma unroll
    for (int off = 1; off < 1024; off <<= 1) {
        int t = (tid >= off) ? sh[tid - off] : 0;
        __syncthreads();
        sh[tid] += t;
        __syncthreads();
    }
    if (i < N_NODES) g_off[i] = sh[tid] - v;
    if (tid == 1023) g_bsum[blockIdx.x] = sh[1023];
}

__global__ void k_scan2() {
    __shared__ int sh[64];
    int tid = threadIdx.x;
    int v = (tid < SCAN_BLOCKS) ? g_bsum[tid] : 0;
    sh[tid] = v;
    __syncthreads();
#pragma unroll
    for (int off = 1; off < 64; off <<= 1) {
        int t = (tid >= off) ? sh[tid - off] : 0;
        __syncthreads();
        sh[tid] += t;
        __syncthreads();
    }
    if (tid < SCAN_BLOCKS) g_bbase[tid] = sh[tid] - v;
    if (tid == 63) g_off[N_NODES] = sh[63];
}

__global__ void k_scan3() {
    int i = blockIdx.x * blockDim.x + threadIdx.x;
    if (i < N_NODES) {
        int o = g_off[i] + g_bbase[i >> 10];
        g_off[i] = o;
        g_cur[i] = o;
    }
}

// ---------------- CSR scatter (grid-strided) ----------------
__global__ void k_scatter(const int* __restrict__ ei) {
    for (int i = blockIdx.x * blockDim.x + threadIdx.x; i < ET; i += gridDim.x * blockDim.x) {
        int s, d;
        if (i < N_EDGES) { s = ei[i]; d = ei[N_EDGES + i]; }
        else             { s = i - N_EDGES; d = s; }
        int pos = atomicAdd(&g_cur[d], 1);
        g_csrc[pos] = s;
    }
}

// ---------------- tensor-core tf32 GEMM + fused attention dots, fp16 h output ----------------
__global__ void __launch_bounds__(256) k_gemm(const float* __restrict__ Xext,
                                              const float* __restrict__ W,
                                              const float* __restrict__ att_s,
                                              const float* __restrict__ att_d) {
    extern __shared__ uint32_t sm[];
    uint32_t* As = sm;                 // [128][68]
    uint32_t* Bs = sm + AS_WORDS;      // [64][136]
    float* as_sm = (float*)(sm + SMEM_WORDS);
    float* ad_sm = as_sm + 128;
    const float* X = Xext ? Xext : (const float*)g_buf;
    const int tid = threadIdx.x;
    const int wid = tid >> 5, lane = tid & 31;
    const int g = lane >> 2, t = lane & 3;
    const int wm = wid & 3, wn = wid >> 2;
    const int row0 = blockIdx.x * 128;

    if (tid < 128)      as_sm[tid] = att_s[tid];
    else                ad_sm[tid - 128] = att_d[tid - 128];

    float d[2][8][4];
#pragma unroll
    for (int mi = 0; mi < 2; mi++)
#pragma unroll
        for (int ni = 0; ni < 8; ni++)
#pragma unroll
            for (int k = 0; k < 4; k++) d[mi][ni][k] = 0.f;

    for (int kc = 0; kc < 128; kc += 64) {
#pragma unroll
        for (int it = 0; it < 8; it++) {
            int idx = tid + it * 256;
            int r = idx >> 4, c4 = (idx & 15) * 4;
            int gr = row0 + r;
            uint32_t o0 = 0, o1 = 0, o2 = 0, o3 = 0;
            if (gr < N_NODES) {
                float4 v = *(const float4*)&X[(size_t)gr * FDIM + kc + c4];
                o0 = f2tf32(v.x); o1 = f2tf32(v.y); o2 = f2tf32(v.z); o3 = f2tf32(v.w);
            }
            uint32_t* p = &As[r * AS_STRIDE + c4];
            p[0] = o0; p[1] = o1; p[2] = o2; p[3] = o3;
        }
#pragma unroll
        for (int it = 0; it < 8; it++) {
            int idx = tid + it * 256;
            int k = idx >> 5, n4 = (idx & 31) * 4;
            float4 v = *(const float4*)&W[(size_t)(kc + k) * FDIM + n4];
            uint32_t* p = &Bs[k * BS_STRIDE + n4];
            p[0] = f2tf32(v.x); p[1] = f2tf32(v.y); p[2] = f2tf32(v.z); p[3] = f2tf32(v.w);
        }
        __syncthreads();

#pragma unroll
        for (int ks = 0; ks < 8; ks++) {
            const int k0 = ks * 8;
            uint32_t a[2][4];
#pragma unroll
            for (int mi = 0; mi < 2; mi++) {
                int rb = wm * 32 + mi * 16;
                a[mi][0] = As[(rb + g) * AS_STRIDE + k0 + t];
                a[mi][1] = As[(rb + g + 8) * AS_STRIDE + k0 + t];
                a[mi][2] = As[(rb + g) * AS_STRIDE + k0 + t + 4];
                a[mi][3] = As[(rb + g + 8) * AS_STRIDE + k0 + t + 4];
            }
#pragma unroll
            for (int ni = 0; ni < 8; ni++) {
                int nb = wn * 64 + ni * 8;
                uint32_t b0 = Bs[(k0 + t) * BS_STRIDE + nb + g];
                uint32_t b1 = Bs[(k0 + t + 4) * BS_STRIDE + nb + g];
                mma16n8k8(d[0][ni], a[0], b0, b1);
                mma16n8k8(d[1][ni], a[1], b0, b1);
            }
        }
        __syncthreads();
    }

    // epilogue: fp16 h store + fused per-head attention dots
    const int h0 = 2 * wn;
#pragma unroll
    for (int mi = 0; mi < 2; mi++) {
        int r0 = row0 + wm * 32 + mi * 16 + g;
        int r1 = r0 + 8;
        float s0a = 0.f, s0b = 0.f, d0a = 0.f, d0b = 0.f;
        float s1a = 0.f, s1b = 0.f, d1a = 0.f, d1b = 0.f;
#pragma unroll
        for (int ni = 0; ni < 8; ni++) {
            int col = wn * 64 + ni * 8 + t * 2;
            float w0s = as_sm[col], w1s = as_sm[col + 1];
            float w0d = ad_sm[col], w1d = ad_sm[col + 1];
            float v00 = d[mi][ni][0], v01 = d[mi][ni][1];
            float v10 = d[mi][ni][2], v11 = d[mi][ni][3];
            if (r0 < N_NODES) g_h16[((size_t)r0 * FDIM + col) >> 1] = __floats2half2_rn(v00, v01);
            if (r1 < N_NODES) g_h16[((size_t)r1 * FDIM + col) >> 1] = __floats2half2_rn(v10, v11);
            if (ni < 4) {
                s0a = fmaf(v00, w0s, fmaf(v01, w1s, s0a));
                d0a = fmaf(v00, w0d, fmaf(v01, w1d, d0a));
                s1a = fmaf(v10, w0s, fmaf(v11, w1s, s1a));
                d1a = fmaf(v10, w0d, fmaf(v11, w1d, d1a));
            } else {
                s0b = fmaf(v00, w0s, fmaf(v01, w1s, s0b));
                d0b = fmaf(v00, w0d, fmaf(v01, w1d, d0b));
                s1b = fmaf(v10, w0s, fmaf(v11, w1s, s1b));
                d1b = fmaf(v10, w0d, fmaf(v11, w1d, d1b));
            }
        }
#pragma unroll
        for (int o = 1; o <= 2; o <<= 1) {
            s0a += __shfl_down_sync(0xffffffffu, s0a, o);
            s0b += __shfl_down_sync(0xffffffffu, s0b, o);
            d0a += __shfl_down_sync(0xffffffffu, d0a, o);
            d0b += __shfl_down_sync(0xffffffffu, d0b, o);
            s1a += __shfl_down_sync(0xffffffffu, s1a, o);
            s1b += __shfl_down_sync(0xffffffffu, s1b, o);
            d1a += __shfl_down_sync(0xffffffffu, d1a, o);
            d1b += __shfl_down_sync(0xffffffffu, d1b, o);
        }
        if (t == 0) {
            if (r0 < N_NODES) {
                g_asrc[r0 * HEADS + h0] = s0a; g_asrc[r0 * HEADS + h0 + 1] = s0b;
                g_adst[r0 * HEADS + h0] = d0a; g_adst[r0 * HEADS + h0 + 1] = d0b;
            }
            if (r1 < N_NODES) {
                g_asrc[r1 * HEADS + h0] = s1a; g_asrc[r1 * HEADS + h0 + 1] = s1b;
                g_adst[r1 * HEADS + h0] = d1a; g_adst[r1 * HEADS + h0 + 1] = d1b;
            }
        }
    }
}

// ---------------- single-pass softmax aggregation (warp per dst node) ----------------
// softmax shift-invariance: out = sum(exp(e)*h) / sum(exp(e)); no max pass needed
// (e = lrelu(a_src+a_dst) is bounded ~|8| for this data scale -> exp safe in fp32).
__global__ void __launch_bounds__(256) k_aggregate(const float* __restrict__ bias) {
    int d = (blockIdx.x * 256 + threadIdx.x) >> 5;
    int lane = threadIdx.x & 31;
    if (d >= N_NODES) return;
    const int beg = g_off[d], end = g_off[d + 1];
    const int myh = lane >> 3;
    const int ch = lane * 4;
    const float adm = g_adst[d * HEADS + myh];
    const float* __restrict__ asr = (const float*)g_asrc;

    float4 acc0 = make_float4(0.f, 0.f, 0.f, 0.f);
    float4 acc1 = make_float4(0.f, 0.f, 0.f, 0.f);
    float den0 = 0.f, den1 = 0.f;
    const int last = end - 1;

    for (int j = beg; j < end; j += 8) {
        int sI[8];
        float vm[8];
#pragma unroll
        for (int u = 0; u < 8; u++) {
            int jj = j + u;
            vm[u] = (jj < end) ? 1.f : 0.f;
            sI[u] = g_csrc[jj < end ? jj : last];
        }
        float w[8];
#pragma unroll
        for (int u = 0; u < 8; u++)
            w[u] = vm[u] * __expf(lrelu(asr[sI[u] * HEADS + myh] + adm));
        uint2 hr[8];
#pragma unroll
        for (int u = 0; u < 8; u++)
            hr[u] = *(const uint2*)&g_h16[((size_t)sI[u] * FDIM + ch) >> 1];
#pragma unroll
        for (int u = 0; u < 8; u += 2) {
            float2 p0 = __half22float2(*(__half2*)&hr[u].x);
            float2 p1 = __half22float2(*(__half2*)&hr[u].y);
            float2 q0 = __half22float2(*(__half2*)&hr[u + 1].x);
            float2 q1 = __half22float2(*(__half2*)&hr[u + 1].y);
            den0 += w[u];
            den1 += w[u + 1];
            acc0.x = fmaf(w[u], p0.x, acc0.x);     acc0.y = fmaf(w[u], p0.y, acc0.y);
            acc0.z = fmaf(w[u], p1.x, acc0.z);     acc0.w = fmaf(w[u], p1.y, acc0.w);
            acc1.x = fmaf(w[u + 1], q0.x, acc1.x); acc1.y = fmaf(w[u + 1], q0.y, acc1.y);
            acc1.z = fmaf(w[u + 1], q1.x, acc1.z); acc1.w = fmaf(w[u + 1], q1.y, acc1.w);
        }
    }
    const float inv = 1.f / (den0 + den1);
    float4 b = *(const float4*)&bias[ch];
    float4 r;
    r.x = fmaxf(fmaf(acc0.x + acc1.x, inv, b.x), 0.f);
    r.y = fmaxf(fmaf(acc0.y + acc1.y, inv, b.y), 0.f);
    r.z = fmaxf(fmaf(acc0.z + acc1.z, inv, b.z), 0.f);
    r.w = fmaxf(fmaf(acc0.w + acc1.w, inv, b.w), 0.f);
    *(float4*)&g_buf[(size_t)d * FDIM + ch] = r;
}

// ---------------- global mean pool + linear head ----------------
__global__ void k_pool(const int* __restrict__ batch,
                       const float* __restrict__ w_lin,
                       const float* __restrict__ b_lin,
                       float* __restrict__ out) {
    int g = blockIdx.x;
    __shared__ int s_lo, s_hi;
    __shared__ float pooled[FDIM];
    if (threadIdx.x == 0) {
        int lo = 0, hi = N_NODES;
        while (lo < hi) { int mid = (lo + hi) >> 1; if (batch[mid] < g) lo = mid + 1; else hi = mid; }
        s_lo = lo;
        hi = N_NODES;
        while (lo < hi) { int mid = (lo + hi) >> 1; if (batch[mid] < g + 1) lo = mid + 1; else hi = mid; }
        s_hi = lo;
    }
    __syncthreads();
    int lo = s_lo, hi = s_hi;
    float a0 = 0.f, a1 = 0.f, a2 = 0.f, a3 = 0.f;
    int n = lo;
    for (; n + 4 <= hi; n += 4) {
        a0 += g_buf[(size_t)(n + 0) * FDIM + threadIdx.x];
        a1 += g_buf[(size_t)(n + 1) * FDIM + threadIdx.x];
        a2 += g_buf[(size_t)(n + 2) * FDIM + threadIdx.x];
        a3 += g_buf[(size_t)(n + 3) * FDIM + threadIdx.x];
    }
    for (; n < hi; n++) a0 += g_buf[(size_t)n * FDIM + threadIdx.x];
    float cnt = (float)(hi - lo);
    pooled[threadIdx.x] = (a0 + a1 + a2 + a3) / fmaxf(cnt, 1.f);
    __syncthreads();
    if (threadIdx.x < OUT_CH) {
        float acc = b_lin[threadIdx.x];
        for (int c = 0; c < FDIM; c++) acc += pooled[c] * w_lin[c * OUT_CH + threadIdx.x];
        out[g * OUT_CH + threadIdx.x] = acc;
    }
}

// ---------------- launch ----------------
extern "C" void kernel_launch(void* const* d_in, const int* in_sizes, int n_in,
                              void* d_out, int out_size) {
    const float* x      = (const float*)d_in[0];
    const int*   ei     = (const int*)d_in[1];
    const int*   batch  = (const int*)d_in[2];
    const float* W1     = (const float*)d_in[3];
    const float* att_s1 = (const float*)d_in[4];
    const float* att_d1 = (const float*)d_in[5];
    const float* b1     = (const float*)d_in[6];
    const float* W2     = (const float*)d_in[7];
    const float* att_s2 = (const float*)d_in[8];
    const float* att_d2 = (const float*)d_in[9];
    const float* b2     = (const float*)d_in[10];
    const float* w_lin  = (const float*)d_in[11];
    const float* b_lin  = (const float*)d_in[12];
    float* out = (float*)d_out;

    cudaFuncSetAttribute(k_gemm, cudaFuncAttributeMaxDynamicSharedMemorySize, SMEM_BYTES);

    const int NB = (N_NODES + 255) / 256;
    const int WB = (N_NODES * 32 + 255) / 256;

    k_init_counts<<<NB, 256>>>();
    k_hist<<<200, 256>>>(ei);
    k_scan1<<<SCAN_BLOCKS, 1024>>>();
    k_scan2<<<1, 64>>>();
    k_scan3<<<NB, 256>>>();
    k_scatter<<<888, 256>>>(ei);

    // layer 1
    k_gemm<<<GEMM_BLOCKS, 256, SMEM_BYTES>>>(x, W1, att_s1, att_d1);
    k_aggregate<<<WB, 256>>>(b1);

    // layer 2
    k_gemm<<<GEMM_BLOCKS, 256, SMEM_BYTES>>>(nullptr, W2, att_s2, att_d2);
    k_aggregate<<<WB, 256>>>(b2);

    k_pool<<<N_GRAPHS, 128>>>(batch, w_lin, b_lin, out);
}

// round 11
// speedup vs baseline: 1.0303x; 1.0303x over previous
#include <cuda_runtime.h>
#include <cuda_fp16.h>
#include <cstdint>

#define N_NODES 50000
#define N_EDGES 800000
#define ET (N_EDGES + N_NODES)
#define FDIM 128
#define HEADS 4
#define N_GRAPHS 64
#define OUT_CH 10
#define NEG 0.2f

#define GEMM_BLOCKS ((N_NODES + 127) / 128)        // 391
#define SCAN_BLOCKS ((N_NODES + 1023) / 1024)      // 49

// fp16 GEMM smem: A[128][136] halves + B[128][136] halves + 256 floats att
#define AH 136
#define A_HALFS (128 * AH)
#define SMEM_BYTES (A_HALFS * 2 * 2 + 1024)        // 70656

// ---------------- scratch ----------------
__device__ __half2 g_h16[(size_t)N_NODES * FDIM / 2];   // h in fp16 (gather source)
__device__ float g_buf[(size_t)N_NODES * FDIM];
__device__ float g_asrc[N_NODES * HEADS];
__device__ float g_adst[N_NODES * HEADS];
__device__ int   g_counts[N_NODES];
__device__ int   g_off[N_NODES + 1];
__device__ int   g_cur[N_NODES];
__device__ int   g_csrc[ET];
__device__ int   g_bsum[64];
__device__ int   g_bbase[64];

__device__ __forceinline__ float lrelu(float x) { return x > 0.f ? x : NEG * x; }
__device__ __forceinline__ uint32_t smem_u32(const void* p) {
    uint32_t a;
    asm("{ .reg .u64 t; cvta.to.shared.u64 t, %1; cvt.u32.u64 %0, t; }" : "=r"(a) : "l"(p));
    return a;
}
__device__ __forceinline__ void ldsm_x4(uint32_t* r, uint32_t addr) {
    asm volatile("ldmatrix.sync.aligned.m8n8.x4.shared.b16 {%0,%1,%2,%3}, [%4];"
        : "=r"(r[0]), "=r"(r[1]), "=r"(r[2]), "=r"(r[3]) : "r"(addr));
}
__device__ __forceinline__ void ldsm_x2t(uint32_t& r0, uint32_t& r1, uint32_t addr) {
    asm volatile("ldmatrix.sync.aligned.m8n8.x2.trans.shared.b16 {%0,%1}, [%2];"
        : "=r"(r0), "=r"(r1) : "r"(addr));
}
__device__ __forceinline__ void mma_f16(float* d, const uint32_t* a, uint32_t b0, uint32_t b1) {
    asm volatile(
        "mma.sync.aligned.m16n8k16.row.col.f32.f16.f16.f32 "
        "{%0,%1,%2,%3}, {%4,%5,%6,%7}, {%8,%9}, {%0,%1,%2,%3};"
        : "+f"(d[0]), "+f"(d[1]), "+f"(d[2]), "+f"(d[3])
        : "r"(a[0]), "r"(a[1]), "r"(a[2]), "r"(a[3]), "r"(b0), "r"(b1));
}
__device__ __forceinline__ uint32_t pack_h2(float a, float b) {
    __half2 h = __floats2half2_rn(a, b);
    return *(uint32_t*)&h;
}

// ---------------- init counts to 1 (self loops pre-counted) ----------------
__global__ void k_init_counts() {
    int i = blockIdx.x * blockDim.x + threadIdx.x;
    if (i < N_NODES) g_counts[i] = 1;
}

// ---------------- degree histogram (vectorized over dst half) ----------------
__global__ void k_hist(const int* __restrict__ ei) {
    const int4* dst4 = (const int4*)(ei + N_EDGES);
    for (int i = blockIdx.x * blockDim.x + threadIdx.x; i < N_EDGES / 4; i += gridDim.x * blockDim.x) {
        int4 d = dst4[i];
        atomicAdd(&g_counts[d.x], 1);
        atomicAdd(&g_counts[d.y], 1);
        atomicAdd(&g_counts[d.z], 1);
        atomicAdd(&g_counts[d.w], 1);
    }
}

// ---------------- parallel 3-phase scan ----------------
__global__ void __launch_bounds__(1024) k_scan1() {
    __shared__ int sh[1024];
    int tid = threadIdx.x;
    int i = blockIdx.x * 1024 + tid;
    int v = (i < N_NODES) ? g_counts[i] : 0;
    sh[tid] = v;
    __syncthreads();
#pragma unroll
    for (int off = 1; off < 1024; off <<= 1) {
        int t = (tid >= off) ? sh[tid - off] : 0;
        __syncthreads();
        sh[tid] += t;
        __syncthreads();
    }
    if (i < N_NODES) g_off[i] = sh[tid] - v;
    if (tid == 1023) g_bsum[blockIdx.x] = sh[1023];
}

__global__ void k_scan2() {
    __shared__ int sh[64];
    int tid = threadIdx.x;
    int v = (tid < SCAN_BLOCKS) ? g_bsum[tid] : 0;
    sh[tid] = v;
    __syncthreads();
#pragma unroll
    for (int off = 1; off < 64; off <<= 1) {
        int t = (tid >= off) ? sh[tid - off] : 0;
        __syncthreads();
        sh[tid] += t;
        __syncthreads();
    }
    if (tid < SCAN_BLOCKS) g_bbase[tid] = sh[tid] - v;
    if (tid == 63) g_off[N_NODES] = sh[63];
}

__global__ void k_scan3() {
    int i = blockIdx.x * blockDim.x + threadIdx.x;
    if (i < N_NODES) {
        int o = g_off[i] + g_bbase[i >> 10];
        g_off[i] = o;
        g_cur[i] = o;
    }
}

// ---------------- CSR scatter (grid-strided) ----------------
__global__ void k_scatter(const int* __restrict__ ei) {
    for (int i = blockIdx.x * blockDim.x + threadIdx.x; i < ET; i += gridDim.x * blockDim.x) {
        int s, d;
        if (i < N_EDGES) { s = ei[i]; d = ei[N_EDGES + i]; }
        else             { s = i - N_EDGES; d = s; }
        int pos = atomicAdd(&g_cur[d], 1);
        g_csrc[pos] = s;
    }
}

// ---------------- fp16 tensor-core GEMM + fused attention dots, fp16 h output ----------------
// g_h16[N,128] = X @ W; accumulation fp32. Full K=128 resident in smem.
__global__ void __launch_bounds__(256) k_gemm(const float* __restrict__ Xext,
                                              const float* __restrict__ W,
                                              const float* __restrict__ att_s,
                                              const float* __restrict__ att_d) {
    extern __shared__ __half smh[];
    __half* As = smh;                    // [128][136]
    __half* Bs = smh + A_HALFS;          // [128][136]  (k-major: row k, col n)
    float* as_sm = (float*)(smh + 2 * A_HALFS);
    float* ad_sm = as_sm + 128;
    const float* X = Xext ? Xext : (const float*)g_buf;
    const int tid = threadIdx.x;
    const int wid = tid >> 5, lane = tid & 31;
    const int g = lane >> 2, t = lane & 3;
    const int wm = wid & 3, wn = wid >> 2;
    const int row0 = blockIdx.x * 128;

    if (tid < 128)      as_sm[tid] = att_s[tid];
    else                ad_sm[tid - 128] = att_d[tid - 128];

    // load A: X rows (fp32 -> fp16)
#pragma unroll
    for (int it = 0; it < 16; it++) {
        int idx = tid + it * 256;          // 0..4095
        int r = idx >> 5, c4 = (idx & 31) * 4;
        int gr = row0 + r;
        uint2 pk = make_uint2(0u, 0u);
        if (gr < N_NODES) {
            float4 v = *(const float4*)&X[(size_t)gr * FDIM + c4];
            pk.x = pack_h2(v.x, v.y);
            pk.y = pack_h2(v.z, v.w);
        }
        *(uint2*)&As[r * AH + c4] = pk;
    }
    // load B: W (fp32 -> fp16), k-major
#pragma unroll
    for (int it = 0; it < 16; it++) {
        int idx = tid + it * 256;
        int k = idx >> 5, n4 = (idx & 31) * 4;
        float4 v = *(const float4*)&W[(size_t)k * FDIM + n4];
        uint2 pk;
        pk.x = pack_h2(v.x, v.y);
        pk.y = pack_h2(v.z, v.w);
        *(uint2*)&Bs[k * AH + n4] = pk;
    }
    __syncthreads();

    const uint32_t sbase = smem_u32(smh);
    // ldmatrix lane addressing
    const int lrow = (lane & 7) + ((lane >> 3) & 1) * 8;     // 0..15
    const int khi  = ((lane >> 4) & 1) * 8;                  // 0/8 (A only)
    uint32_t aaddr0 = sbase + (uint32_t)(((wm * 32 + 0)  + lrow) * AH + khi) * 2;
    uint32_t aaddr1 = sbase + (uint32_t)(((wm * 32 + 16) + lrow) * AH + khi) * 2;
    uint32_t baddr  = sbase + (uint32_t)(A_HALFS + (lane & 15) * AH + wn * 64) * 2;

    float d[2][8][4];
#pragma unroll
    for (int mi = 0; mi < 2; mi++)
#pragma unroll
        for (int ni = 0; ni < 8; ni++)
#pragma unroll
            for (int k = 0; k < 4; k++) d[mi][ni][k] = 0.f;

#pragma unroll
    for (int ks = 0; ks < 8; ks++) {
        uint32_t a[2][4];
        ldsm_x4(a[0], aaddr0 + ks * 32);          // 16 halves = 32B per kstep
        ldsm_x4(a[1], aaddr1 + ks * 32);
        uint32_t bk = baddr + (uint32_t)(ks * 16 * AH) * 2;
#pragma unroll
        for (int ni = 0; ni < 8; ni++) {
            uint32_t b0, b1;
            ldsm_x2t(b0, b1, bk + ni * 16);       // 8 halves = 16B per ni
            mma_f16(d[0][ni], a[0], b0, b1);
            mma_f16(d[1][ni], a[1], b0, b1);
        }
    }

    // epilogue: fp16 h store + fused per-head attention dots
    const int h0 = 2 * wn;
#pragma unroll
    for (int mi = 0; mi < 2; mi++) {
        int r0 = row0 + wm * 32 + mi * 16 + g;
        int r1 = r0 + 8;
        float s0a = 0.f, s0b = 0.f, d0a = 0.f, d0b = 0.f;
        float s1a = 0.f, s1b = 0.f, d1a = 0.f, d1b = 0.f;
#pragma unroll
        for (int ni = 0; ni < 8; ni++) {
            int col = wn * 64 + ni * 8 + t * 2;
            float w0s = as_sm[col], w1s = as_sm[col + 1];
            float w0d = ad_sm[col], w1d = ad_sm[col + 1];
            float v00 = d[mi][ni][0], v01 = d[mi][ni][1];
            float v10 = d[mi][ni][2], v11 = d[mi][ni][3];
            if (r0 < N_NODES) *(uint32_t*)&g_h16[((size_t)r0 * FDIM + col) >> 1] = pack_h2(v00, v01);
            if (r1 < N_NODES) *(uint32_t*)&g_h16[((size_t)r1 * FDIM + col) >> 1] = pack_h2(v10, v11);
            if (ni < 4) {
                s0a = fmaf(v00, w0s, fmaf(v01, w1s, s0a));
                d0a = fmaf(v00, w0d, fmaf(v01, w1d, d0a));
                s1a = fmaf(v10, w0s, fmaf(v11, w1s, s1a));
                d1a = fmaf(v10, w0d, fmaf(v11, w1d, d1a));
            } else {
                s0b = fmaf(v00, w0s, fmaf(v01, w1s, s0b));
                d0b = fmaf(v00, w0d, fmaf(v01, w1d, d0b));
                s1b = fmaf(v10, w0s, fmaf(v11, w1s, s1b));
                d1b = fmaf(v10, w0d, fmaf(v11, w1d, d1b));
            }
        }
#pragma unroll
        for (int o = 1; o <= 2; o <<= 1) {
            s0a += __shfl_down_sync(0xffffffffu, s0a, o);
            s0b += __shfl_down_sync(0xffffffffu, s0b, o);
            d0a += __shfl_down_sync(0xffffffffu, d0a, o);
            d0b += __shfl_down_sync(0xffffffffu, d0b, o);
            s1a += __shfl_down_sync(0xffffffffu, s1a, o);
            s1b += __shfl_down_sync(0xffffffffu, s1b, o);
            d1a += __shfl_down_sync(0xffffffffu, d1a, o);
            d1b += __shfl_down_sync(0xffffffffu, d1b, o);
        }
        if (t == 0) {
            if (r0 < N_NODES) {
                g_asrc[r0 * HEADS + h0] = s0a; g_asrc[r0 * HEADS + h0 + 1] = s0b;
                g_adst[r0 * HEADS + h0] = d0a; g_adst[r0 * HEADS + h0 + 1] = d0b;
            }
            if (r1 < N_NODES) {
                g_asrc[r1 * HEADS + h0] = s1a; g_asrc[r1 * HEADS + h0 + 1] = s1b;
                g_adst[r1 * HEADS + h0] = d1a; g_adst[r1 * HEADS + h0 + 1] = d1b;
            }
        }
    }
}

// ---------------- single-pass softmax aggregation (warp per dst node) ----------------
__global__ void __launch_bounds__(256) k_aggregate(const float* __restrict__ bias) {
    int d = (blockIdx.x * 256 + threadIdx.x) >> 5;
    int lane = threadIdx.x & 31;
    if (d >= N_NODES) return;
    const int beg = g_off[d], end = g_off[d + 1];
    const int myh = lane >> 3;
    const int ch = lane * 4;
    const float adm = g_adst[d * HEADS + myh];
    const float* __restrict__ asr = (const float*)g_asrc;

    float4 acc0 = make_float4(0.f, 0.f, 0.f, 0.f);
    float4 acc1 = make_float4(0.f, 0.f, 0.f, 0.f);
    float den0 = 0.f, den1 = 0.f;
    const int last = end - 1;

    for (int j = beg; j < end; j += 8) {
        int sI[8];
        float vm[8];
#pragma unroll
        for (int u = 0; u < 8; u++) {
            int jj = j + u;
            vm[u] = (jj < end) ? 1.f : 0.f;
            sI[u] = g_csrc[jj < end ? jj : last];
        }
        float w[8];
#pragma unroll
        for (int u = 0; u < 8; u++)
            w[u] = vm[u] * __expf(lrelu(asr[sI[u] * HEADS + myh] + adm));
        uint2 hr[8];
#pragma unroll
        for (int u = 0; u < 8; u++)
            hr[u] = *(const uint2*)&g_h16[((size_t)sI[u] * FDIM + ch) >> 1];
#pragma unroll
        for (int u = 0; u < 8; u += 2) {
            float2 p0 = __half22float2(*(__half2*)&hr[u].x);
            float2 p1 = __half22float2(*(__half2*)&hr[u].y);
            float2 q0 = __half22float2(*(__half2*)&hr[u + 1].x);
            float2 q1 = __half22float2(*(__half2*)&hr[u + 1].y);
            den0 += w[u];
            den1 += w[u + 1];
            acc0.x = fmaf(w[u], p0.x, acc0.x);     acc0.y = fmaf(w[u], p0.y, acc0.y);
            acc0.z = fmaf(w[u], p1.x, acc0.z);     acc0.w = fmaf(w[u], p1.y, acc0.w);
            acc1.x = fmaf(w[u + 1], q0.x, acc1.x); acc1.y = fmaf(w[u + 1], q0.y, acc1.y);
            acc1.z = fmaf(w[u + 1], q1.x, acc1.z); acc1.w = fmaf(w[u + 1], q1.y, acc1.w);
        }
    }
    const float inv = 1.f / (den0 + den1);
    float4 b = *(const float4*)&bias[ch];
    float4 r;
    r.x = fmaxf(fmaf(acc0.x + acc1.x, inv, b.x), 0.f);
    r.y = fmaxf(fmaf(acc0.y + acc1.y, inv, b.y), 0.f);
    r.z = fmaxf(fmaf(acc0.z + acc1.z, inv, b.z), 0.f);
    r.w = fmaxf(fmaf(acc0.w + acc1.w, inv, b.w), 0.f);
    *(float4*)&g_buf[(size_t)d * FDIM + ch] = r;
}

// ---------------- global mean pool + linear head ----------------
__global__ void k_pool(const int* __restrict__ batch,
                       const float* __restrict__ w_lin,
                       const float* __restrict__ b_lin,
                       float* __restrict__ out) {
    int g = blockIdx.x;
    __shared__ int s_lo, s_hi;
    __shared__ float pooled[FDIM];
    if (threadIdx.x == 0) {
        int lo = 0, hi = N_NODES;
        while (lo < hi) { int mid = (lo + hi) >> 1; if (batch[mid] < g) lo = mid + 1; else hi = mid; }
        s_lo = lo;
        hi = N_NODES;
        while (lo < hi) { int mid = (lo + hi) >> 1; if (batch[mid] < g + 1) lo = mid + 1; else hi = mid; }
        s_hi = lo;
    }
    __syncthreads();
    int lo = s_lo, hi = s_hi;
    float a0 = 0.f, a1 = 0.f, a2 = 0.f, a3 = 0.f;
    int n = lo;
    for (; n + 4 <= hi; n += 4) {
        a0 += g_buf[(size_t)(n + 0) * FDIM + threadIdx.x];
        a1 += g_buf[(size_t)(n + 1) * FDIM + threadIdx.x];
        a2 += g_buf[(size_t)(n + 2) * FDIM + threadIdx.x];
        a3 += g_buf[(size_t)(n + 3) * FDIM + threadIdx.x];
    }
    for (; n < hi; n++) a0 += g_buf[(size_t)n * FDIM + threadIdx.x];
    float cnt = (float)(hi - lo);
    pooled[threadIdx.x] = (a0 + a1 + a2 + a3) / fmaxf(cnt, 1.f);
    __syncthreads();
    if (threadIdx.x < OUT_CH) {
        float acc = b_lin[threadIdx.x];
        for (int c = 0; c < FDIM; c++) acc += pooled[c] * w_lin[c * OUT_CH + threadIdx.x];
        out[g * OUT_CH + threadIdx.x] = acc;
    }
}

// ---------------- launch ----------------
extern "C" void kernel_launch(void* const* d_in, const int* in_sizes, int n_in,
                              void* d_out, int out_size) {
    const float* x      = (const float*)d_in[0];
    const int*   ei     = (const int*)d_in[1];
    const int*   batch  = (const int*)d_in[2];
    const float* W1     = (const float*)d_in[3];
    const float* att_s1 = (const float*)d_in[4];
    const float* att_d1 = (const float*)d_in[5];
    const float* b1     = (const float*)d_in[6];
    const float* W2     = (const float*)d_in[7];
    const float* att_s2 = (const float*)d_in[8];
    const float* att_d2 = (const float*)d_in[9];
    const float* b2     = (const float*)d_in[10];
    const float* w_lin  = (const float*)d_in[11];
    const float* b_lin  = (const float*)d_in[12];
    float* out = (float*)d_out;

    cudaFuncSetAttribute(k_gemm, cudaFuncAttributeMaxDynamicSharedMemorySize, SMEM_BYTES);

    const int NB = (N_NODES + 255) / 256;
    const int WB = (N_NODES * 32 + 255) / 256;

    k_init_counts<<<NB, 256>>>();                                       // 1
    k_hist<<<200, 256>>>(ei);                                           // 2
    k_scan1<<<SCAN_BLOCKS, 1024>>>();                                   // 3
    k_gemm<<<GEMM_BLOCKS, 256, SMEM_BYTES>>>(x, W1, att_s1, att_d1);    // 4 <- profiled
    k_scan2<<<1, 64>>>();                                               // 5
    k_scan3<<<NB, 256>>>();                                             // 6
    k_scatter<<<888, 256>>>(ei);                                        // 7
    k_aggregate<<<WB, 256>>>(b1);                                       // 8

    k_gemm<<<GEMM_BLOCKS, 256, SMEM_BYTES>>>(nullptr, W2, att_s2, att_d2);
    k_aggregate<<<WB, 256>>>(b2);

    k_pool<<<N_GRAPHS, 128>>>(batch, w_lin, b_lin, out);
}

// round 13
// speedup vs baseline: 1.0752x; 1.0436x over previous
#include <cuda_runtime.h>
#include <cuda_fp16.h>
#include <cstdint>

#define N_NODES 50000
#define N_EDGES 800000
#define ET (N_EDGES + N_NODES)
#define FDIM 128
#define HEADS 4
#define N_GRAPHS 64
#define OUT_CH 10
#define NEG 0.2f

#define GEMM_BLOCKS ((N_NODES + 127) / 128)        // 391
#define HIST_TAIL 148
#define SCAN_BLOCKS ((N_NODES + 1023) / 1024)      // 49

// fp16 GEMM smem: A[128][136] halves + B[128][136] halves + 256 floats att
#define AH 136
#define A_HALFS (128 * AH)
#define SMEM_BYTES (A_HALFS * 2 * 2 + 1024)        // 70656

// ---------------- scratch ----------------
__device__ __half2 g_h16[(size_t)N_NODES * FDIM / 2];
__device__ float g_buf[(size_t)N_NODES * FDIM];
__device__ float g_asrc[N_NODES * HEADS];
__device__ float g_adst[N_NODES * HEADS];
__device__ int   g_counts[N_NODES];                // zeroed by k_scan each run (and statically)
__device__ int   g_off[N_NODES + 1];
__device__ int   g_cur[N_NODES];
__device__ int   g_csrc[ET];
// decoupled-lookback state: (flag << 32) | value, flag: 0 invalid / 1 aggregate / 2 prefix.
// Single 64-bit word => flag+value read/written atomically; no fence needed.
__device__ __align__(8) unsigned long long g_state[SCAN_BLOCKS];

__device__ __forceinline__ float lrelu(float x) { return x > 0.f ? x : NEG * x; }
__device__ __forceinline__ uint32_t smem_u32(const void* p) {
    uint32_t a;
    asm("{ .reg .u64 t; cvta.to.shared.u64 t, %1; cvt.u32.u64 %0, t; }" : "=r"(a) : "l"(p));
    return a;
}
__device__ __forceinline__ void ldsm_x4(uint32_t* r, uint32_t addr) {
    asm volatile("ldmatrix.sync.aligned.m8n8.x4.shared.b16 {%0,%1,%2,%3}, [%4];"
        : "=r"(r[0]), "=r"(r[1]), "=r"(r[2]), "=r"(r[3]) : "r"(addr));
}
__device__ __forceinline__ void ldsm_x2t(uint32_t& r0, uint32_t& r1, uint32_t addr) {
    asm volatile("ldmatrix.sync.aligned.m8n8.x2.trans.shared.b16 {%0,%1}, [%2];"
        : "=r"(r0), "=r"(r1) : "r"(addr));
}
__device__ __forceinline__ void mma_f16(float* d, const uint32_t* a, uint32_t b0, uint32_t b1) {
    asm volatile(
        "mma.sync.aligned.m16n8k16.row.col.f32.f16.f16.f32 "
        "{%0,%1,%2,%3}, {%4,%5,%6,%7}, {%8,%9}, {%0,%1,%2,%3};"
        : "+f"(d[0]), "+f"(d[1]), "+f"(d[2]), "+f"(d[3])
        : "r"(a[0]), "r"(a[1]), "r"(a[2]), "r"(a[3]), "r"(b0), "r"(b1));
}
__device__ __forceinline__ uint32_t pack_h2(float a, float b) {
    __half2 h = __floats2half2_rn(a, b);
    return *(uint32_t*)&h;
}

// ---------------- fp16 tensor-core GEMM + fused attdot + (optional) hist tail ----------------
__global__ void __launch_bounds__(256, 2) k_gemm_hist(const float* __restrict__ Xext,
                                                      const float* __restrict__ W,
                                                      const float* __restrict__ att_s,
                                                      const float* __restrict__ att_d,
                                                      const int* __restrict__ ei) {
    if (blockIdx.x >= GEMM_BLOCKS) {
        if (ei) {   // degree histogram over edge dst (counts pre-zeroed)
            const int4* dst4 = (const int4*)(ei + N_EDGES);
            for (int i = (blockIdx.x - GEMM_BLOCKS) * 256 + threadIdx.x; i < N_EDGES / 4;
                 i += HIST_TAIL * 256) {
                int4 d = dst4[i];
                atomicAdd(&g_counts[d.x], 1);
                atomicAdd(&g_counts[d.y], 1);
                atomicAdd(&g_counts[d.z], 1);
                atomicAdd(&g_counts[d.w], 1);
            }
        }
        return;
    }
    extern __shared__ __half smh[];
    __half* As = smh;                    // [128][136]
    __half* Bs = smh + A_HALFS;          // [128][136] k-major
    float* as_sm = (float*)(smh + 2 * A_HALFS);
    float* ad_sm = as_sm + 128;
    const float* X = Xext ? Xext : (const float*)g_buf;
    const int tid = threadIdx.x;
    const int wid = tid >> 5, lane = tid & 31;
    const int g = lane >> 2, t = lane & 3;
    const int wm = wid & 3, wn = wid >> 2;
    const int row0 = blockIdx.x * 128;

    if (tid < 128)      as_sm[tid] = att_s[tid];
    else                ad_sm[tid - 128] = att_d[tid - 128];

#pragma unroll
    for (int it = 0; it < 16; it++) {
        int idx = tid + it * 256;
        int r = idx >> 5, c4 = (idx & 31) * 4;
        int gr = row0 + r;
        uint2 pk = make_uint2(0u, 0u);
        if (gr < N_NODES) {
            float4 v = *(const float4*)&X[(size_t)gr * FDIM + c4];
            pk.x = pack_h2(v.x, v.y);
            pk.y = pack_h2(v.z, v.w);
        }
        *(uint2*)&As[r * AH + c4] = pk;
    }
#pragma unroll
    for (int it = 0; it < 16; it++) {
        int idx = tid + it * 256;
        int k = idx >> 5, n4 = (idx & 31) * 4;
        float4 v = *(const float4*)&W[(size_t)k * FDIM + n4];
        uint2 pk;
        pk.x = pack_h2(v.x, v.y);
        pk.y = pack_h2(v.z, v.w);
        *(uint2*)&Bs[k * AH + n4] = pk;
    }
    __syncthreads();

    const uint32_t sbase = smem_u32(smh);
    const int lrow = (lane & 7) + ((lane >> 3) & 1) * 8;
    const int khi  = ((lane >> 4) & 1) * 8;
    uint32_t aaddr0 = sbase + (uint32_t)(((wm * 32 + 0)  + lrow) * AH + khi) * 2;
    uint32_t aaddr1 = sbase + (uint32_t)(((wm * 32 + 16) + lrow) * AH + khi) * 2;
    uint32_t baddr  = sbase + (uint32_t)(A_HALFS + (lane & 15) * AH + wn * 64) * 2;

    float d[2][8][4];
#pragma unroll
    for (int mi = 0; mi < 2; mi++)
#pragma unroll
        for (int ni = 0; ni < 8; ni++)
#pragma unroll
            for (int k = 0; k < 4; k++) d[mi][ni][k] = 0.f;

#pragma unroll
    for (int ks = 0; ks < 8; ks++) {
        uint32_t a[2][4];
        ldsm_x4(a[0], aaddr0 + ks * 32);
        ldsm_x4(a[1], aaddr1 + ks * 32);
        uint32_t bk = baddr + (uint32_t)(ks * 16 * AH) * 2;
#pragma unroll
        for (int ni = 0; ni < 8; ni++) {
            uint32_t b0, b1;
            ldsm_x2t(b0, b1, bk + ni * 16);
            mma_f16(d[0][ni], a[0], b0, b1);
            mma_f16(d[1][ni], a[1], b0, b1);
        }
    }

    const int h0 = 2 * wn;
#pragma unroll
    for (int mi = 0; mi < 2; mi++) {
        int r0 = row0 + wm * 32 + mi * 16 + g;
        int r1 = r0 + 8;
        float s0a = 0.f, s0b = 0.f, d0a = 0.f, d0b = 0.f;
        float s1a = 0.f, s1b = 0.f, d1a = 0.f, d1b = 0.f;
#pragma unroll
        for (int ni = 0; ni < 8; ni++) {
            int col = wn * 64 + ni * 8 + t * 2;
            float w0s = as_sm[col], w1s = as_sm[col + 1];
            float w0d = ad_sm[col], w1d = ad_sm[col + 1];
            float v00 = d[mi][ni][0], v01 = d[mi][ni][1];
            float v10 = d[mi][ni][2], v11 = d[mi][ni][3];
            if (r0 < N_NODES) *(uint32_t*)&g_h16[((size_t)r0 * FDIM + col) >> 1] = pack_h2(v00, v01);
            if (r1 < N_NODES) *(uint32_t*)&g_h16[((size_t)r1 * FDIM + col) >> 1] = pack_h2(v10, v11);
            if (ni < 4) {
                s0a = fmaf(v00, w0s, fmaf(v01, w1s, s0a));
                d0a = fmaf(v00, w0d, fmaf(v01, w1d, d0a));
                s1a = fmaf(v10, w0s, fmaf(v11, w1s, s1a));
                d1a = fmaf(v10, w0d, fmaf(v11, w1d, d1a));
            } else {
                s0b = fmaf(v00, w0s, fmaf(v01, w1s, s0b));
                d0b = fmaf(v00, w0d, fmaf(v01, w1d, d0b));
                s1b = fmaf(v10, w0s, fmaf(v11, w1s, s1b));
                d1b = fmaf(v10, w0d, fmaf(v11, w1d, d1b));
            }
        }
#pragma unroll
        for (int o = 1; o <= 2; o <<= 1) {
            s0a += __shfl_down_sync(0xffffffffu, s0a, o);
            s0b += __shfl_down_sync(0xffffffffu, s0b, o);
            d0a += __shfl_down_sync(0xffffffffu, d0a, o);
            d0b += __shfl_down_sync(0xffffffffu, d0b, o);
            s1a += __shfl_down_sync(0xffffffffu, s1a, o);
            s1b += __shfl_down_sync(0xffffffffu, s1b, o);
            d1a += __shfl_down_sync(0xffffffffu, d1a, o);
            d1b += __shfl_down_sync(0xffffffffu, d1b, o);
        }
        if (t == 0) {
            if (r0 < N_NODES) {
                g_asrc[r0 * HEADS + h0] = s0a; g_asrc[r0 * HEADS + h0 + 1] = s0b;
                g_adst[r0 * HEADS + h0] = d0a; g_adst[r0 * HEADS + h0 + 1] = d0b;
            }
            if (r1 < N_NODES) {
                g_asrc[r1 * HEADS + h0] = s1a; g_asrc[r1 * HEADS + h0 + 1] = s1b;
                g_adst[r1 * HEADS + h0] = d1a; g_adst[r1 * HEADS + h0 + 1] = d1b;
            }
        }
    }
}

// ---------------- single-kernel decoupled-lookback scan (packed-word protocol) ----------------
// counts+1 (implicit self loop) -> exclusive offsets; writes self-loop into CSR slot 0,
// sets g_cur = off+1, zeroes g_counts for the next replay.
__global__ void __launch_bounds__(1024) k_scan() {
    __shared__ int sh[1024];
    __shared__ int s_base;
    const int bid = blockIdx.x, tid = threadIdx.x;
    const int i = bid * 1024 + tid;
    int v = 0;
    if (i < N_NODES) {
        v = g_counts[i] + 1;       // +1 self loop
        g_counts[i] = 0;           // reset for next replay
    }
    sh[tid] = v;
    __syncthreads();
#pragma unroll
    for (int off = 1; off < 1024; off <<= 1) {
        int t = (tid >= off) ? sh[tid - off] : 0;
        __syncthreads();
        sh[tid] += t;
        __syncthreads();
    }
    const int total = sh[1023];

    if (tid == 0) {
        volatile unsigned long long* st = (volatile unsigned long long*)g_state;
        if (bid == 0) {
            st[0] = (2ull << 32) | (unsigned)total;   // inclusive prefix
            s_base = 0;
        } else {
            st[bid] = (1ull << 32) | (unsigned)total; // aggregate
            int run = 0;
            int j = bid - 1;
            while (true) {
                unsigned long long s = st[j];         // flag+value in ONE word: atomic
                unsigned f = (unsigned)(s >> 32);
                if (f == 2u) { run += (int)(unsigned)s; break; }
                if (f == 1u) { run += (int)(unsigned)s; j--; }
            }
            st[bid] = (2ull << 32) | (unsigned)(run + total);
            s_base = run;
        }
    }
    __syncthreads();
    const int base = s_base;
    if (i < N_NODES) {
        int o = base + sh[tid] - v;   // exclusive
        g_off[i] = o;
        g_csrc[o] = i;                // self loop in slot 0
        g_cur[i] = o + 1;
        if (i == N_NODES - 1) g_off[N_NODES] = o + v;
    }
}

// ---------------- CSR scatter (real edges only) + lookback-state reset ----------------
__global__ void k_scatter(const int* __restrict__ ei) {
    int gi = blockIdx.x * blockDim.x + threadIdx.x;
    if (gi < SCAN_BLOCKS) g_state[gi] = 0ull;   // reset for next replay
    for (int i = gi; i < N_EDGES; i += gridDim.x * blockDim.x) {
        int s = ei[i], d = ei[N_EDGES + i];
        int pos = atomicAdd(&g_cur[d], 1);
        g_csrc[pos] = s;
    }
}

// ---------------- single-pass softmax aggregation (warp per dst node) ----------------
__global__ void __launch_bounds__(256) k_aggregate(const float* __restrict__ bias) {
    int d = (blockIdx.x * 256 + threadIdx.x) >> 5;
    int lane = threadIdx.x & 31;
    if (d >= N_NODES) return;
    const int beg = g_off[d], end = g_off[d + 1];
    const int myh = lane >> 3;
    const int ch = lane * 4;
    const float adm = g_adst[d * HEADS + myh];
    const float* __restrict__ asr = (const float*)g_asrc;

    float4 acc0 = make_float4(0.f, 0.f, 0.f, 0.f);
    float4 acc1 = make_float4(0.f, 0.f, 0.f, 0.f);
    float den0 = 0.f, den1 = 0.f;
    const int last = end - 1;

    for (int j = beg; j < end; j += 8) {
        int sI[8];
        float vm[8];
#pragma unroll
        for (int u = 0; u < 8; u++) {
            int jj = j + u;
            vm[u] = (jj < end) ? 1.f : 0.f;
            sI[u] = g_csrc[jj < end ? jj : last];
        }
        float w[8];
#pragma unroll
        for (int u = 0; u < 8; u++)
            w[u] = vm[u] * __expf(lrelu(asr[sI[u] * HEADS + myh] + adm));
        uint2 hr[8];
#pragma unroll
        for (int u = 0; u < 8; u++)
            hr[u] = *(const uint2*)&g_h16[((size_t)sI[u] * FDIM + ch) >> 1];
#pragma unroll
        for (int u = 0; u < 8; u += 2) {
            float2 p0 = __half22float2(*(__half2*)&hr[u].x);
            float2 p1 = __half22float2(*(__half2*)&hr[u].y);
            float2 q0 = __half22float2(*(__half2*)&hr[u + 1].x);
            float2 q1 = __half22float2(*(__half2*)&hr[u + 1].y);
            den0 += w[u];
            den1 += w[u + 1];
            acc0.x = fmaf(w[u], p0.x, acc0.x);     acc0.y = fmaf(w[u], p0.y, acc0.y);
            acc0.z = fmaf(w[u], p1.x, acc0.z);     acc0.w = fmaf(w[u], p1.y, acc0.w);
            acc1.x = fmaf(w[u + 1], q0.x, acc1.x); acc1.y = fmaf(w[u + 1], q0.y, acc1.y);
            acc1.z = fmaf(w[u + 1], q1.x, acc1.z); acc1.w = fmaf(w[u + 1], q1.y, acc1.w);
        }
    }
    const float inv = 1.f / (den0 + den1);
    float4 b = *(const float4*)&bias[ch];
    float4 r;
    r.x = fmaxf(fmaf(acc0.x + acc1.x, inv, b.x), 0.f);
    r.y = fmaxf(fmaf(acc0.y + acc1.y, inv, b.y), 0.f);
    r.z = fmaxf(fmaf(acc0.z + acc1.z, inv, b.z), 0.f);
    r.w = fmaxf(fmaf(acc0.w + acc1.w, inv, b.w), 0.f);
    *(float4*)&g_buf[(size_t)d * FDIM + ch] = r;
}

// ---------------- global mean pool + linear head ----------------
__global__ void k_pool(const int* __restrict__ batch,
                       const float* __restrict__ w_lin,
                       const float* __restrict__ b_lin,
                       float* __restrict__ out) {
    int g = blockIdx.x;
    __shared__ int s_lo, s_hi;
    __shared__ float pooled[FDIM];
    if (threadIdx.x == 0) {
        int lo = 0, hi = N_NODES;
        while (lo < hi) { int mid = (lo + hi) >> 1; if (batch[mid] < g) lo = mid + 1; else hi = mid; }
        s_lo = lo;
        hi = N_NODES;
        while (lo < hi) { int mid = (lo + hi) >> 1; if (batch[mid] < g + 1) lo = mid + 1; else hi = mid; }
        s_hi = lo;
    }
    __syncthreads();
    int lo = s_lo, hi = s_hi;
    float a0 = 0.f, a1 = 0.f, a2 = 0.f, a3 = 0.f;
    int n = lo;
    for (; n + 4 <= hi; n += 4) {
        a0 += g_buf[(size_t)(n + 0) * FDIM + threadIdx.x];
        a1 += g_buf[(size_t)(n + 1) * FDIM + threadIdx.x];
        a2 += g_buf[(size_t)(n + 2) * FDIM + threadIdx.x];
        a3 += g_buf[(size_t)(n + 3) * FDIM + threadIdx.x];
    }
    for (; n < hi; n++) a0 += g_buf[(size_t)n * FDIM + threadIdx.x];
    float cnt = (float)(hi - lo);
    pooled[threadIdx.x] = (a0 + a1 + a2 + a3) / fmaxf(cnt, 1.f);
    __syncthreads();
    if (threadIdx.x < OUT_CH) {
        float acc = b_lin[threadIdx.x];
        for (int c = 0; c < FDIM; c++) acc += pooled[c] * w_lin[c * OUT_CH + threadIdx.x];
        out[g * OUT_CH + threadIdx.x] = acc;
    }
}

// ---------------- launch (7 kernels) ----------------
extern "C" void kernel_launch(void* const* d_in, const int* in_sizes, int n_in,
                              void* d_out, int out_size) {
    const float* x      = (const float*)d_in[0];
    const int*   ei     = (const int*)d_in[1];
    const int*   batch  = (const int*)d_in[2];
    const float* W1     = (const float*)d_in[3];
    const float* att_s1 = (const float*)d_in[4];
    const float* att_d1 = (const float*)d_in[5];
    const float* b1     = (const float*)d_in[6];
    const float* W2     = (const float*)d_in[7];
    const float* att_s2 = (const float*)d_in[8];
    const float* att_d2 = (const float*)d_in[9];
    const float* b2     = (const float*)d_in[10];
    const float* w_lin  = (const float*)d_in[11];
    const float* b_lin  = (const float*)d_in[12];
    float* out = (float*)d_out;

    cudaFuncSetAttribute(k_gemm_hist, cudaFuncAttributeMaxDynamicSharedMemorySize, SMEM_BYTES);

    const int WB = (N_NODES * 32 + 255) / 256;

    // 1: GEMM layer1 + histogram (overlapped)
    k_gemm_hist<<<GEMM_BLOCKS + HIST_TAIL, 256, SMEM_BYTES>>>(x, W1, att_s1, att_d1, ei);
    // 2: single-kernel scan (+self loops, +cur init, +counts reset)
    k_scan<<<SCAN_BLOCKS, 1024>>>();
    // 3: edge scatter (+state reset)
    k_scatter<<<888, 256>>>(ei);
    // 4: aggregate layer1  <- profiled launch
    k_aggregate<<<WB, 256>>>(b1);
    // 5: GEMM layer2
    k_gemm_hist<<<GEMM_BLOCKS, 256, SMEM_BYTES>>>(nullptr, W2, att_s2, att_d2, nullptr);
    // 6: aggregate layer2
    k_aggregate<<<WB, 256>>>(b2);
    // 7: pool + head
    k_pool<<<N_GRAPHS, 128>>>(batch, w_lin, b_lin, out);
}

// round 14
// speedup vs baseline: 1.1331x; 1.0539x over previous
#include <cuda_runtime.h>
#include <cuda_fp16.h>
#include <cstdint>

#define N_NODES 50000
#define N_EDGES 800000
#define ET (N_EDGES + N_NODES)
#define FDIM 128
#define HEADS 4
#define N_GRAPHS 64
#define OUT_CH 10
#define NEG 0.2f

#define GEMM_BLOCKS ((N_NODES + 127) / 128)        // 391
#define HIST_TAIL 148
#define SCAN_BLOCKS ((N_NODES + 1023) / 1024)      // 49

// fp16 GEMM smem: A[128][136] halves + B[128][136] halves + 256 floats att
#define AH 136
#define A_HALFS (128 * AH)
#define SMEM_BYTES (A_HALFS * 2 * 2 + 1024)        // 70656

// ---------------- scratch ----------------
__device__ __half2 g_h16[(size_t)N_NODES * FDIM / 2];
__device__ float g_buf[(size_t)N_NODES * FDIM];
__device__ float g_asrc[N_NODES * HEADS];
__device__ float g_adst[N_NODES * HEADS];
__device__ int   g_counts[N_NODES];                // zeroed by k_scan each run (and statically)
__device__ int   g_off[N_NODES + 1];
__device__ int   g_cur[N_NODES];
__device__ int   g_csrc[ET];
// decoupled-lookback state: (flag << 32) | value, flag: 0 invalid / 1 aggregate / 2 prefix.
__device__ __align__(8) unsigned long long g_state[SCAN_BLOCKS];

__device__ __forceinline__ float lrelu(float x) { return x > 0.f ? x : NEG * x; }
__device__ __forceinline__ uint32_t smem_u32(const void* p) {
    uint32_t a;
    asm("{ .reg .u64 t; cvta.to.shared.u64 t, %1; cvt.u32.u64 %0, t; }" : "=r"(a) : "l"(p));
    return a;
}
__device__ __forceinline__ void ldsm_x4(uint32_t* r, uint32_t addr) {
    asm volatile("ldmatrix.sync.aligned.m8n8.x4.shared.b16 {%0,%1,%2,%3}, [%4];"
        : "=r"(r[0]), "=r"(r[1]), "=r"(r[2]), "=r"(r[3]) : "r"(addr));
}
__device__ __forceinline__ void ldsm_x2t(uint32_t& r0, uint32_t& r1, uint32_t addr) {
    asm volatile("ldmatrix.sync.aligned.m8n8.x2.trans.shared.b16 {%0,%1}, [%2];"
        : "=r"(r0), "=r"(r1) : "r"(addr));
}
__device__ __forceinline__ void mma_f16(float* d, const uint32_t* a, uint32_t b0, uint32_t b1) {
    asm volatile(
        "mma.sync.aligned.m16n8k16.row.col.f32.f16.f16.f32 "
        "{%0,%1,%2,%3}, {%4,%5,%6,%7}, {%8,%9}, {%0,%1,%2,%3};"
        : "+f"(d[0]), "+f"(d[1]), "+f"(d[2]), "+f"(d[3])
        : "r"(a[0]), "r"(a[1]), "r"(a[2]), "r"(a[3]), "r"(b0), "r"(b1));
}
__device__ __forceinline__ uint32_t pack_h2(float a, float b) {
    __half2 h = __floats2half2_rn(a, b);
    return *(uint32_t*)&h;
}

// ---------------- fp16 tensor-core GEMM + fused attdot + (optional) hist tail ----------------
__global__ void __launch_bounds__(256, 2) k_gemm_hist(const float* __restrict__ Xext,
                                                      const float* __restrict__ W,
                                                      const float* __restrict__ att_s,
                                                      const float* __restrict__ att_d,
                                                      const int* __restrict__ ei) {
    if (blockIdx.x >= GEMM_BLOCKS) {
        if (ei) {
            const int4* dst4 = (const int4*)(ei + N_EDGES);
            for (int i = (blockIdx.x - GEMM_BLOCKS) * 256 + threadIdx.x; i < N_EDGES / 4;
                 i += HIST_TAIL * 256) {
                int4 d = dst4[i];
                atomicAdd(&g_counts[d.x], 1);
                atomicAdd(&g_counts[d.y], 1);
                atomicAdd(&g_counts[d.z], 1);
                atomicAdd(&g_counts[d.w], 1);
            }
        }
        return;
    }
    extern __shared__ __half smh[];
    __half* As = smh;                    // [128][136]
    __half* Bs = smh + A_HALFS;          // [128][136] k-major
    float* as_sm = (float*)(smh + 2 * A_HALFS);
    float* ad_sm = as_sm + 128;
    const float* X = Xext ? Xext : (const float*)g_buf;
    const int tid = threadIdx.x;
    const int wid = tid >> 5, lane = tid & 31;
    const int g = lane >> 2, t = lane & 3;
    const int wm = wid & 3, wn = wid >> 2;
    const int row0 = blockIdx.x * 128;

    if (tid < 128)      as_sm[tid] = att_s[tid];
    else                ad_sm[tid - 128] = att_d[tid - 128];

#pragma unroll
    for (int it = 0; it < 16; it++) {
        int idx = tid + it * 256;
        int r = idx >> 5, c4 = (idx & 31) * 4;
        int gr = row0 + r;
        uint2 pk = make_uint2(0u, 0u);
        if (gr < N_NODES) {
            float4 v = *(const float4*)&X[(size_t)gr * FDIM + c4];
            pk.x = pack_h2(v.x, v.y);
            pk.y = pack_h2(v.z, v.w);
        }
        *(uint2*)&As[r * AH + c4] = pk;
    }
#pragma unroll
    for (int it = 0; it < 16; it++) {
        int idx = tid + it * 256;
        int k = idx >> 5, n4 = (idx & 31) * 4;
        float4 v = *(const float4*)&W[(size_t)k * FDIM + n4];
        uint2 pk;
        pk.x = pack_h2(v.x, v.y);
        pk.y = pack_h2(v.z, v.w);
        *(uint2*)&Bs[k * AH + n4] = pk;
    }
    __syncthreads();

    const uint32_t sbase = smem_u32(smh);
    const int lrow = (lane & 7) + ((lane >> 3) & 1) * 8;
    const int khi  = ((lane >> 4) & 1) * 8;
    uint32_t aaddr0 = sbase + (uint32_t)(((wm * 32 + 0)  + lrow) * AH + khi) * 2;
    uint32_t aaddr1 = sbase + (uint32_t)(((wm * 32 + 16) + lrow) * AH + khi) * 2;
    uint32_t baddr  = sbase + (uint32_t)(A_HALFS + (lane & 15) * AH + wn * 64) * 2;

    float d[2][8][4];
#pragma unroll
    for (int mi = 0; mi < 2; mi++)
#pragma unroll
        for (int ni = 0; ni < 8; ni++)
#pragma unroll
            for (int k = 0; k < 4; k++) d[mi][ni][k] = 0.f;

#pragma unroll
    for (int ks = 0; ks < 8; ks++) {
        uint32_t a[2][4];
        ldsm_x4(a[0], aaddr0 + ks * 32);
        ldsm_x4(a[1], aaddr1 + ks * 32);
        uint32_t bk = baddr + (uint32_t)(ks * 16 * AH) * 2;
#pragma unroll
        for (int ni = 0; ni < 8; ni++) {
            uint32_t b0, b1;
            ldsm_x2t(b0, b1, bk + ni * 16);
            mma_f16(d[0][ni], a[0], b0, b1);
            mma_f16(d[1][ni], a[1], b0, b1);
        }
    }

    const int h0 = 2 * wn;
#pragma unroll
    for (int mi = 0; mi < 2; mi++) {
        int r0 = row0 + wm * 32 + mi * 16 + g;
        int r1 = r0 + 8;
        float s0a = 0.f, s0b = 0.f, d0a = 0.f, d0b = 0.f;
        float s1a = 0.f, s1b = 0.f, d1a = 0.f, d1b = 0.f;
#pragma unroll
        for (int ni = 0; ni < 8; ni++) {
            int col = wn * 64 + ni * 8 + t * 2;
            float w0s = as_sm[col], w1s = as_sm[col + 1];
            float w0d = ad_sm[col], w1d = ad_sm[col + 1];
            float v00 = d[mi][ni][0], v01 = d[mi][ni][1];
            float v10 = d[mi][ni][2], v11 = d[mi][ni][3];
            if (r0 < N_NODES) *(uint32_t*)&g_h16[((size_t)r0 * FDIM + col) >> 1] = pack_h2(v00, v01);
            if (r1 < N_NODES) *(uint32_t*)&g_h16[((size_t)r1 * FDIM + col) >> 1] = pack_h2(v10, v11);
            if (ni < 4) {
                s0a = fmaf(v00, w0s, fmaf(v01, w1s, s0a));
                d0a = fmaf(v00, w0d, fmaf(v01, w1d, d0a));
                s1a = fmaf(v10, w0s, fmaf(v11, w1s, s1a));
                d1a = fmaf(v10, w0d, fmaf(v11, w1d, d1a));
            } else {
                s0b = fmaf(v00, w0s, fmaf(v01, w1s, s0b));
                d0b = fmaf(v00, w0d, fmaf(v01, w1d, d0b));
                s1b = fmaf(v10, w0s, fmaf(v11, w1s, s1b));
                d1b = fmaf(v10, w0d, fmaf(v11, w1d, d1b));
            }
        }
#pragma unroll
        for (int o = 1; o <= 2; o <<= 1) {
            s0a += __shfl_down_sync(0xffffffffu, s0a, o);
            s0b += __shfl_down_sync(0xffffffffu, s0b, o);
            d0a += __shfl_down_sync(0xffffffffu, d0a, o);
            d0b += __shfl_down_sync(0xffffffffu, d0b, o);
            s1a += __shfl_down_sync(0xffffffffu, s1a, o);
            s1b += __shfl_down_sync(0xffffffffu, s1b, o);
            d1a += __shfl_down_sync(0xffffffffu, d1a, o);
            d1b += __shfl_down_sync(0xffffffffu, d1b, o);
        }
        if (t == 0) {
            if (r0 < N_NODES) {
                g_asrc[r0 * HEADS + h0] = s0a; g_asrc[r0 * HEADS + h0 + 1] = s0b;
                g_adst[r0 * HEADS + h0] = d0a; g_adst[r0 * HEADS + h0 + 1] = d0b;
            }
            if (r1 < N_NODES) {
                g_asrc[r1 * HEADS + h0] = s1a; g_asrc[r1 * HEADS + h0 + 1] = s1b;
                g_adst[r1 * HEADS + h0] = d1a; g_adst[r1 * HEADS + h0 + 1] = d1b;
            }
        }
    }
}

// ---------------- single-kernel decoupled-lookback scan (packed-word protocol) ----------------
__global__ void __launch_bounds__(1024) k_scan() {
    __shared__ int sh[1024];
    __shared__ int s_base;
    const int bid = blockIdx.x, tid = threadIdx.x;
    const int i = bid * 1024 + tid;
    int v = 0;
    if (i < N_NODES) {
        v = g_counts[i] + 1;       // +1 self loop
        g_counts[i] = 0;           // reset for next replay
    }
    sh[tid] = v;
    __syncthreads();
#pragma unroll
    for (int off = 1; off < 1024; off <<= 1) {
        int t = (tid >= off) ? sh[tid - off] : 0;
        __syncthreads();
        sh[tid] += t;
        __syncthreads();
    }
    const int total = sh[1023];

    if (tid == 0) {
        volatile unsigned long long* st = (volatile unsigned long long*)g_state;
        if (bid == 0) {
            st[0] = (2ull << 32) | (unsigned)total;
            s_base = 0;
        } else {
            st[bid] = (1ull << 32) | (unsigned)total;
            int run = 0;
            int j = bid - 1;
            while (true) {
                unsigned long long s = st[j];
                unsigned f = (unsigned)(s >> 32);
                if (f == 2u) { run += (int)(unsigned)s; break; }
                if (f == 1u) { run += (int)(unsigned)s; j--; }
            }
            st[bid] = (2ull << 32) | (unsigned)(run + total);
            s_base = run;
        }
    }
    __syncthreads();
    const int base = s_base;
    if (i < N_NODES) {
        int o = base + sh[tid] - v;
        g_off[i] = o;
        g_csrc[o] = i;                // self loop in slot 0
        g_cur[i] = o + 1;
        if (i == N_NODES - 1) g_off[N_NODES] = o + v;
    }
}

// ---------------- CSR scatter (real edges only) + lookback-state reset ----------------
__global__ void k_scatter(const int* __restrict__ ei) {
    int gi = blockIdx.x * blockDim.x + threadIdx.x;
    if (gi < SCAN_BLOCKS) g_state[gi] = 0ull;
    for (int i = gi; i < N_EDGES; i += gridDim.x * blockDim.x) {
        int s = ei[i], d = ei[N_EDGES + i];
        int pos = atomicAdd(&g_cur[d], 1);
        g_csrc[pos] = s;
    }
}

// ---------------- warp-cooperative single-pass softmax aggregation ----------------
// 8 edges/batch x 4 heads = 32 (edge,head) pairs: lane (h*8+u) computes the weight for
// edge u / head h ONCE (1 csrc load, 1 asrc load, 1 exp per lane); shfl distributes.
__global__ void __launch_bounds__(256) k_aggregate(const float* __restrict__ bias) {
    int d = (blockIdx.x * 256 + threadIdx.x) >> 5;
    int lane = threadIdx.x & 31;
    if (d >= N_NODES) return;
    const int beg = g_off[d], end = g_off[d + 1];
    const int myh = lane >> 3;             // head this lane accumulates AND computes weights for
    const int u_of = lane & 7;             // edge slot this lane computes the weight for
    const int ch = lane * 4;
    const float adm = g_adst[d * HEADS + myh];
    const float* __restrict__ asr = (const float*)g_asrc;
    const int wsrc = (lane & 24);          // base lane of my head group

    float4 acc0 = make_float4(0.f, 0.f, 0.f, 0.f);
    float4 acc1 = make_float4(0.f, 0.f, 0.f, 0.f);
    float den = 0.f;
    const int last = end - 1;

    for (int j = beg; j < end; j += 8) {
        // one (edge,head) weight per lane
        int jj = j + u_of;
        int sOwn = g_csrc[jj < end ? jj : last];
        float aOwn = asr[sOwn * HEADS + myh];
        float wOwn = (jj < end) ? __expf(lrelu(aOwn + adm)) : 0.f;

        // distribute src indices and weights
        int sU[8];
        float wU[8];
#pragma unroll
        for (int u = 0; u < 8; u++) {
            sU[u] = __shfl_sync(0xffffffffu, sOwn, u);
            wU[u] = __shfl_sync(0xffffffffu, wOwn, wsrc | u);
        }
        uint2 hr[8];
#pragma unroll
        for (int u = 0; u < 8; u++)
            hr[u] = *(const uint2*)&g_h16[((size_t)sU[u] * FDIM + ch) >> 1];
#pragma unroll
        for (int u = 0; u < 8; u += 2) {
            float2 p0 = __half22float2(*(__half2*)&hr[u].x);
            float2 p1 = __half22float2(*(__half2*)&hr[u].y);
            float2 q0 = __half22float2(*(__half2*)&hr[u + 1].x);
            float2 q1 = __half22float2(*(__half2*)&hr[u + 1].y);
            den += wU[u] + wU[u + 1];
            acc0.x = fmaf(wU[u], p0.x, acc0.x);     acc0.y = fmaf(wU[u], p0.y, acc0.y);
            acc0.z = fmaf(wU[u], p1.x, acc0.z);     acc0.w = fmaf(wU[u], p1.y, acc0.w);
            acc1.x = fmaf(wU[u + 1], q0.x, acc1.x); acc1.y = fmaf(wU[u + 1], q0.y, acc1.y);
            acc1.z = fmaf(wU[u + 1], q1.x, acc1.z); acc1.w = fmaf(wU[u + 1], q1.y, acc1.w);
        }
    }
    const float inv = 1.f / den;
    float4 b = *(const float4*)&bias[ch];
    float4 r;
    r.x = fmaxf(fmaf(acc0.x + acc1.x, inv, b.x), 0.f);
    r.y = fmaxf(fmaf(acc0.y + acc1.y, inv, b.y), 0.f);
    r.z = fmaxf(fmaf(acc0.z + acc1.z, inv, b.z), 0.f);
    r.w = fmaxf(fmaf(acc0.w + acc1.w, inv, b.w), 0.f);
    *(float4*)&g_buf[(size_t)d * FDIM + ch] = r;
}

// ---------------- global mean pool + linear head ----------------
__global__ void k_pool(const int* __restrict__ batch,
                       const float* __restrict__ w_lin,
                       const float* __restrict__ b_lin,
                       float* __restrict__ out) {
    int g = blockIdx.x;
    __shared__ int s_lo, s_hi;
    __shared__ float pooled[FDIM];
    if (threadIdx.x == 0) {
        int lo = 0, hi = N_NODES;
        while (lo < hi) { int mid = (lo + hi) >> 1; if (batch[mid] < g) lo = mid + 1; else hi = mid; }
        s_lo = lo;
        hi = N_NODES;
        while (lo < hi) { int mid = (lo + hi) >> 1; if (batch[mid] < g + 1) lo = mid + 1; else hi = mid; }
        s_hi = lo;
    }
    __syncthreads();
    int lo = s_lo, hi = s_hi;
    float a0 = 0.f, a1 = 0.f, a2 = 0.f, a3 = 0.f;
    int n = lo;
    for (; n + 4 <= hi; n += 4) {
        a0 += g_buf[(size_t)(n + 0) * FDIM + threadIdx.x];
        a1 += g_buf[(size_t)(n + 1) * FDIM + threadIdx.x];
        a2 += g_buf[(size_t)(n + 2) * FDIM + threadIdx.x];
        a3 += g_buf[(size_t)(n + 3) * FDIM + threadIdx.x];
    }
    for (; n < hi; n++) a0 += g_buf[(size_t)n * FDIM + threadIdx.x];
    float cnt = (float)(hi - lo);
    pooled[threadIdx.x] = (a0 + a1 + a2 + a3) / fmaxf(cnt, 1.f);
    __syncthreads();
    if (threadIdx.x < OUT_CH) {
        float acc = b_lin[threadIdx.x];
        for (int c = 0; c < FDIM; c++) acc += pooled[c] * w_lin[c * OUT_CH + threadIdx.x];
        out[g * OUT_CH + threadIdx.x] = acc;
    }
}

// ---------------- launch (7 kernels) ----------------
extern "C" void kernel_launch(void* const* d_in, const int* in_sizes, int n_in,
                              void* d_out, int out_size) {
    const float* x      = (const float*)d_in[0];
    const int*   ei     = (const int*)d_in[1];
    const int*   batch  = (const int*)d_in[2];
    const float* W1     = (const float*)d_in[3];
    const float* att_s1 = (const float*)d_in[4];
    const float* att_d1 = (const float*)d_in[5];
    const float* b1     = (const float*)d_in[6];
    const float* W2     = (const float*)d_in[7];
    const float* att_s2 = (const float*)d_in[8];
    const float* att_d2 = (const float*)d_in[9];
    const float* b2     = (const float*)d_in[10];
    const float* w_lin  = (const float*)d_in[11];
    const float* b_lin  = (const float*)d_in[12];
    float* out = (float*)d_out;

    cudaFuncSetAttribute(k_gemm_hist, cudaFuncAttributeMaxDynamicSharedMemorySize, SMEM_BYTES);

    const int WB = (N_NODES * 32 + 255) / 256;

    k_gemm_hist<<<GEMM_BLOCKS + HIST_TAIL, 256, SMEM_BYTES>>>(x, W1, att_s1, att_d1, ei);
    k_scan<<<SCAN_BLOCKS, 1024>>>();
    k_scatter<<<888, 256>>>(ei);
    k_aggregate<<<WB, 256>>>(b1);          // 4 <- profiled
    k_gemm_hist<<<GEMM_BLOCKS, 256, SMEM_BYTES>>>(nullptr, W2, att_s2, att_d2, nullptr);
    k_aggregate<<<WB, 256>>>(b2);
    k_pool<<<N_GRAPHS, 128>>>(batch, w_lin, b_lin, out);
}

// round 15
// speedup vs baseline: 1.2510x; 1.1040x over previous
#include <cuda_runtime.h>
#include <cuda_fp16.h>
#include <cstdint>

#define N_NODES 50000
#define N_EDGES 800000
#define ET (N_EDGES + N_NODES)
#define FDIM 128
#define HEADS 4
#define N_GRAPHS 64
#define OUT_CH 10
#define NEG 0.2f

#define GEMM_BLOCKS ((N_NODES + 127) / 128)        // 391
#define HIST_TAIL 148
#define SCAN_BLOCKS ((N_NODES + 1023) / 1024)      // 49

// fp16 GEMM smem: A[128][136] halves + B[128][136] halves + 256 floats att
#define AH 136
#define A_HALFS (128 * AH)
#define SMEM_BYTES (A_HALFS * 2 * 2 + 1024)        // 70656

// ---------------- scratch ----------------
__device__ __half2 g_h16[(size_t)N_NODES * FDIM / 2];   // GEMM output (gather source)
__device__ __half2 g_b16[(size_t)N_NODES * FDIM / 2];   // layer output (next GEMM input / pool)
__device__ float g_asrc[N_NODES * HEADS];
__device__ float g_adst[N_NODES * HEADS];
__device__ int   g_counts[N_NODES];                // zeroed by k_scan each run (and statically)
__device__ int   g_off[N_NODES + 1];
__device__ int   g_cur[N_NODES];
__device__ int   g_csrc[ET];
// decoupled-lookback state: (flag << 32) | value, flag: 0 invalid / 1 aggregate / 2 prefix.
__device__ __align__(8) unsigned long long g_state[SCAN_BLOCKS];

__device__ __forceinline__ float lrelu(float x) { return x > 0.f ? x : NEG * x; }
__device__ __forceinline__ uint32_t smem_u32(const void* p) {
    uint32_t a;
    asm("{ .reg .u64 t; cvta.to.shared.u64 t, %1; cvt.u32.u64 %0, t; }" : "=r"(a) : "l"(p));
    return a;
}
__device__ __forceinline__ void ldsm_x4(uint32_t* r, uint32_t addr) {
    asm volatile("ldmatrix.sync.aligned.m8n8.x4.shared.b16 {%0,%1,%2,%3}, [%4];"
        : "=r"(r[0]), "=r"(r[1]), "=r"(r[2]), "=r"(r[3]) : "r"(addr));
}
__device__ __forceinline__ void ldsm_x2t(uint32_t& r0, uint32_t& r1, uint32_t addr) {
    asm volatile("ldmatrix.sync.aligned.m8n8.x2.trans.shared.b16 {%0,%1}, [%2];"
        : "=r"(r0), "=r"(r1) : "r"(addr));
}
__device__ __forceinline__ void mma_f16(float* d, const uint32_t* a, uint32_t b0, uint32_t b1) {
    asm volatile(
        "mma.sync.aligned.m16n8k16.row.col.f32.f16.f16.f32 "
        "{%0,%1,%2,%3}, {%4,%5,%6,%7}, {%8,%9}, {%0,%1,%2,%3};"
        : "+f"(d[0]), "+f"(d[1]), "+f"(d[2]), "+f"(d[3])
        : "r"(a[0]), "r"(a[1]), "r"(a[2]), "r"(a[3]), "r"(b0), "r"(b1));
}
__device__ __forceinline__ uint32_t pack_h2(float a, float b) {
    __half2 h = __floats2half2_rn(a, b);
    return *(uint32_t*)&h;
}

// ---------------- fp16 tensor-core GEMM + fused attdot + (optional) hist tail ----------------
__global__ void __launch_bounds__(256, 2) k_gemm_hist(const float* __restrict__ Xext,
                                                      const float* __restrict__ W,
                                                      const float* __restrict__ att_s,
                                                      const float* __restrict__ att_d,
                                                      const int* __restrict__ ei) {
    if (blockIdx.x >= GEMM_BLOCKS) {
        if (ei) {
            const int4* dst4 = (const int4*)(ei + N_EDGES);
            for (int i = (blockIdx.x - GEMM_BLOCKS) * 256 + threadIdx.x; i < N_EDGES / 4;
                 i += HIST_TAIL * 256) {
                int4 d = dst4[i];
                atomicAdd(&g_counts[d.x], 1);
                atomicAdd(&g_counts[d.y], 1);
                atomicAdd(&g_counts[d.z], 1);
                atomicAdd(&g_counts[d.w], 1);
            }
        }
        return;
    }
    extern __shared__ __half smh[];
    __half* As = smh;                    // [128][136]
    __half* Bs = smh + A_HALFS;          // [128][136] k-major
    float* as_sm = (float*)(smh + 2 * A_HALFS);
    float* ad_sm = as_sm + 128;
    const int tid = threadIdx.x;
    const int wid = tid >> 5, lane = tid & 31;
    const int g = lane >> 2, t = lane & 3;
    const int wm = wid & 3, wn = wid >> 2;
    const int row0 = blockIdx.x * 128;

    if (tid < 128)      as_sm[tid] = att_s[tid];
    else                ad_sm[tid - 128] = att_d[tid - 128];

    if (Xext) {      // layer 1: fp32 input, convert
#pragma unroll
        for (int it = 0; it < 16; it++) {
            int idx = tid + it * 256;
            int r = idx >> 5, c4 = (idx & 31) * 4;
            int gr = row0 + r;
            uint2 pk = make_uint2(0u, 0u);
            if (gr < N_NODES) {
                float4 v = *(const float4*)&Xext[(size_t)gr * FDIM + c4];
                pk.x = pack_h2(v.x, v.y);
                pk.y = pack_h2(v.z, v.w);
            }
            *(uint2*)&As[r * AH + c4] = pk;
        }
    } else {         // layer 2: fp16 input, raw copy
#pragma unroll
        for (int it = 0; it < 16; it++) {
            int idx = tid + it * 256;
            int r = idx >> 5, c4 = (idx & 31) * 4;
            int gr = row0 + r;
            uint2 pk = make_uint2(0u, 0u);
            if (gr < N_NODES)
                pk = *(const uint2*)&g_b16[((size_t)gr * FDIM + c4) >> 1];
            *(uint2*)&As[r * AH + c4] = pk;
        }
    }
#pragma unroll
    for (int it = 0; it < 16; it++) {
        int idx = tid + it * 256;
        int k = idx >> 5, n4 = (idx & 31) * 4;
        float4 v = *(const float4*)&W[(size_t)k * FDIM + n4];
        uint2 pk;
        pk.x = pack_h2(v.x, v.y);
        pk.y = pack_h2(v.z, v.w);
        *(uint2*)&Bs[k * AH + n4] = pk;
    }
    __syncthreads();

    const uint32_t sbase = smem_u32(smh);
    const int lrow = (lane & 7) + ((lane >> 3) & 1) * 8;
    const int khi  = ((lane >> 4) & 1) * 8;
    uint32_t aaddr0 = sbase + (uint32_t)(((wm * 32 + 0)  + lrow) * AH + khi) * 2;
    uint32_t aaddr1 = sbase + (uint32_t)(((wm * 32 + 16) + lrow) * AH + khi) * 2;
    uint32_t baddr  = sbase + (uint32_t)(A_HALFS + (lane & 15) * AH + wn * 64) * 2;

    float d[2][8][4];
#pragma unroll
    for (int mi = 0; mi < 2; mi++)
#pragma unroll
        for (int ni = 0; ni < 8; ni++)
#pragma unroll
            for (int k = 0; k < 4; k++) d[mi][ni][k] = 0.f;

#pragma unroll
    for (int ks = 0; ks < 8; ks++) {
        uint32_t a[2][4];
        ldsm_x4(a[0], aaddr0 + ks * 32);
        ldsm_x4(a[1], aaddr1 + ks * 32);
        uint32_t bk = baddr + (uint32_t)(ks * 16 * AH) * 2;
#pragma unroll
        for (int ni = 0; ni < 8; ni++) {
            uint32_t b0, b1;
            ldsm_x2t(b0, b1, bk + ni * 16);
            mma_f16(d[0][ni], a[0], b0, b1);
            mma_f16(d[1][ni], a[1], b0, b1);
        }
    }

    const int h0 = 2 * wn;
#pragma unroll
    for (int mi = 0; mi < 2; mi++) {
        int r0 = row0 + wm * 32 + mi * 16 + g;
        int r1 = r0 + 8;
        float s0a = 0.f, s0b = 0.f, d0a = 0.f, d0b = 0.f;
        float s1a = 0.f, s1b = 0.f, d1a = 0.f, d1b = 0.f;
#pragma unroll
        for (int ni = 0; ni < 8; ni++) {
            int col = wn * 64 + ni * 8 + t * 2;
            float w0s = as_sm[col], w1s = as_sm[col + 1];
            float w0d = ad_sm[col], w1d = ad_sm[col + 1];
            float v00 = d[mi][ni][0], v01 = d[mi][ni][1];
            float v10 = d[mi][ni][2], v11 = d[mi][ni][3];
            if (r0 < N_NODES) *(uint32_t*)&g_h16[((size_t)r0 * FDIM + col) >> 1] = pack_h2(v00, v01);
            if (r1 < N_NODES) *(uint32_t*)&g_h16[((size_t)r1 * FDIM + col) >> 1] = pack_h2(v10, v11);
            if (ni < 4) {
                s0a = fmaf(v00, w0s, fmaf(v01, w1s, s0a));
                d0a = fmaf(v00, w0d, fmaf(v01, w1d, d0a));
                s1a = fmaf(v10, w0s, fmaf(v11, w1s, s1a));
                d1a = fmaf(v10, w0d, fmaf(v11, w1d, d1a));
            } else {
                s0b = fmaf(v00, w0s, fmaf(v01, w1s, s0b));
                d0b = fmaf(v00, w0d, fmaf(v01, w1d, d0b));
                s1b = fmaf(v10, w0s, fmaf(v11, w1s, s1b));
                d1b = fmaf(v10, w0d, fmaf(v11, w1d, d1b));
            }
        }
#pragma unroll
        for (int o = 1; o <= 2; o <<= 1) {
            s0a += __shfl_down_sync(0xffffffffu, s0a, o);
            s0b += __shfl_down_sync(0xffffffffu, s0b, o);
            d0a += __shfl_down_sync(0xffffffffu, d0a, o);
            d0b += __shfl_down_sync(0xffffffffu, d0b, o);
            s1a += __shfl_down_sync(0xffffffffu, s1a, o);
            s1b += __shfl_down_sync(0xffffffffu, s1b, o);
            d1a += __shfl_down_sync(0xffffffffu, d1a, o);
            d1b += __shfl_down_sync(0xffffffffu, d1b, o);
        }
        if (t == 0) {
            if (r0 < N_NODES) {
                g_asrc[r0 * HEADS + h0] = s0a; g_asrc[r0 * HEADS + h0 + 1] = s0b;
                g_adst[r0 * HEADS + h0] = d0a; g_adst[r0 * HEADS + h0 + 1] = d0b;
            }
            if (r1 < N_NODES) {
                g_asrc[r1 * HEADS + h0] = s1a; g_asrc[r1 * HEADS + h0 + 1] = s1b;
                g_adst[r1 * HEADS + h0] = d1a; g_adst[r1 * HEADS + h0 + 1] = d1b;
            }
        }
    }
}

// ---------------- single-kernel decoupled-lookback scan (packed-word protocol) ----------------
__global__ void __launch_bounds__(1024) k_scan() {
    __shared__ int sh[1024];
    __shared__ int s_base;
    const int bid = blockIdx.x, tid = threadIdx.x;
    const int i = bid * 1024 + tid;
    int v = 0;
    if (i < N_NODES) {
        v = g_counts[i] + 1;       // +1 self loop
        g_counts[i] = 0;           // reset for next replay
    }
    sh[tid] = v;
    __syncthreads();
#pragma unroll
    for (int off = 1; off < 1024; off <<= 1) {
        int t = (tid >= off) ? sh[tid - off] : 0;
        __syncthreads();
        sh[tid] += t;
        __syncthreads();
    }
    const int total = sh[1023];

    if (tid == 0) {
        volatile unsigned long long* st = (volatile unsigned long long*)g_state;
        if (bid == 0) {
            st[0] = (2ull << 32) | (unsigned)total;
            s_base = 0;
        } else {
            st[bid] = (1ull << 32) | (unsigned)total;
            int run = 0;
            int j = bid - 1;
            while (true) {
                unsigned long long s = st[j];
                unsigned f = (unsigned)(s >> 32);
                if (f == 2u) { run += (int)(unsigned)s; break; }
                if (f == 1u) { run += (int)(unsigned)s; j--; }
            }
            st[bid] = (2ull << 32) | (unsigned)(run + total);
            s_base = run;
        }
    }
    __syncthreads();
    const int base = s_base;
    if (i < N_NODES) {
        int o = base + sh[tid] - v;
        g_off[i] = o;
        g_csrc[o] = i;                // self loop in slot 0
        g_cur[i] = o + 1;
        if (i == N_NODES - 1) g_off[N_NODES] = o + v;
    }
}

// ---------------- CSR scatter (real edges only) + lookback-state reset ----------------
__global__ void k_scatter(const int* __restrict__ ei) {
    int gi = blockIdx.x * blockDim.x + threadIdx.x;
    if (gi < SCAN_BLOCKS) g_state[gi] = 0ull;
    for (int i = gi; i < N_EDGES; i += gridDim.x * blockDim.x) {
        int s = ei[i], d = ei[N_EDGES + i];
        int pos = atomicAdd(&g_cur[d], 1);
        g_csrc[pos] = s;
    }
}

// ---------------- warp-cooperative, software-pipelined softmax aggregation ----------------
__global__ void __launch_bounds__(256) k_aggregate(const float* __restrict__ bias) {
    int d = (blockIdx.x * 256 + threadIdx.x) >> 5;
    int lane = threadIdx.x & 31;
    if (d >= N_NODES) return;
    const int beg = g_off[d], end = g_off[d + 1];
    const int myh = lane >> 3;
    const int u_of = lane & 7;
    const int ch = lane * 4;
    const float adm = g_adst[d * HEADS + myh];
    const float* __restrict__ asr = (const float*)g_asrc;
    const int wsrc = (lane & 24);

    float4 acc0 = make_float4(0.f, 0.f, 0.f, 0.f);
    float4 acc1 = make_float4(0.f, 0.f, 0.f, 0.f);
    float den = 0.f;
    const int last = end - 1;

    // prologue: load batch 0's (edge,head) score
    int jj0 = beg + u_of;
    int  sOwn = g_csrc[jj0 < end ? jj0 : last];
    float aOwn = asr[sOwn * HEADS + myh];
    bool  vOwn = jj0 < end;

    for (int j = beg; j < end; j += 8) {
        float wOwn = vOwn ? __expf(lrelu(aOwn + adm)) : 0.f;

        int sU[8];
        float wU[8];
#pragma unroll
        for (int u = 0; u < 8; u++) {
            sU[u] = __shfl_sync(0xffffffffu, sOwn, u);
            wU[u] = __shfl_sync(0xffffffffu, wOwn, wsrc | u);
        }

        // prefetch next batch's own score (overlaps with h gather + math below)
        int jn = j + 8;
        if (jn < end) {
            int jj = jn + u_of;
            vOwn = jj < end;
            sOwn = g_csrc[jj < end ? jj : last];
            aOwn = asr[sOwn * HEADS + myh];
        }

        uint2 hr[8];
#pragma unroll
        for (int u = 0; u < 8; u++)
            hr[u] = *(const uint2*)&g_h16[((size_t)sU[u] * FDIM + ch) >> 1];
#pragma unroll
        for (int u = 0; u < 8; u += 2) {
            float2 p0 = __half22float2(*(__half2*)&hr[u].x);
            float2 p1 = __half22float2(*(__half2*)&hr[u].y);
            float2 q0 = __half22float2(*(__half2*)&hr[u + 1].x);
            float2 q1 = __half22float2(*(__half2*)&hr[u + 1].y);
            den += wU[u] + wU[u + 1];
            acc0.x = fmaf(wU[u], p0.x, acc0.x);     acc0.y = fmaf(wU[u], p0.y, acc0.y);
            acc0.z = fmaf(wU[u], p1.x, acc0.z);     acc0.w = fmaf(wU[u], p1.y, acc0.w);
            acc1.x = fmaf(wU[u + 1], q0.x, acc1.x); acc1.y = fmaf(wU[u + 1], q0.y, acc1.y);
            acc1.z = fmaf(wU[u + 1], q1.x, acc1.z); acc1.w = fmaf(wU[u + 1], q1.y, acc1.w);
        }
    }
    const float inv = 1.f / den;
    float4 b = *(const float4*)&bias[ch];
    float rx = fmaxf(fmaf(acc0.x + acc1.x, inv, b.x), 0.f);
    float ry = fmaxf(fmaf(acc0.y + acc1.y, inv, b.y), 0.f);
    float rz = fmaxf(fmaf(acc0.z + acc1.z, inv, b.z), 0.f);
    float rw = fmaxf(fmaf(acc0.w + acc1.w, inv, b.w), 0.f);
    uint2 outp;
    outp.x = pack_h2(rx, ry);
    outp.y = pack_h2(rz, rw);
    *(uint2*)&g_b16[((size_t)d * FDIM + ch) >> 1] = outp;
}

// ---------------- global mean pool + linear head (fp16 input) ----------------
__global__ void k_pool(const int* __restrict__ batch,
                       const float* __restrict__ w_lin,
                       const float* __restrict__ b_lin,
                       float* __restrict__ out) {
    int g = blockIdx.x;
    __shared__ int s_lo, s_hi;
    __shared__ float pooled[FDIM];
    if (threadIdx.x == 0) {
        int lo = 0, hi = N_NODES;
        while (lo < hi) { int mid = (lo + hi) >> 1; if (batch[mid] < g) lo = mid + 1; else hi = mid; }
        s_lo = lo;
        hi = N_NODES;
        while (lo < hi) { int mid = (lo + hi) >> 1; if (batch[mid] < g + 1) lo = mid + 1; else hi = mid; }
        s_hi = lo;
    }
    __syncthreads();
    int lo = s_lo, hi = s_hi;
    const __half* hb = (const __half*)g_b16;
    float a0 = 0.f, a1 = 0.f, a2 = 0.f, a3 = 0.f;
    int n = lo;
    for (; n + 4 <= hi; n += 4) {
        a0 += __half2float(hb[(size_t)(n + 0) * FDIM + threadIdx.x]);
        a1 += __half2float(hb[(size_t)(n + 1) * FDIM + threadIdx.x]);
        a2 += __half2float(hb[(size_t)(n + 2) * FDIM + threadIdx.x]);
        a3 += __half2float(hb[(size_t)(n + 3) * FDIM + threadIdx.x]);
    }
    for (; n < hi; n++) a0 += __half2float(hb[(size_t)n * FDIM + threadIdx.x]);
    float cnt = (float)(hi - lo);
    pooled[threadIdx.x] = (a0 + a1 + a2 + a3) / fmaxf(cnt, 1.f);
    __syncthreads();
    if (threadIdx.x < OUT_CH) {
        float acc = b_lin[threadIdx.x];
        for (int c = 0; c < FDIM; c++) acc += pooled[c] * w_lin[c * OUT_CH + threadIdx.x];
        out[g * OUT_CH + threadIdx.x] = acc;
    }
}

// ---------------- launch (7 kernels) ----------------
extern "C" void kernel_launch(void* const* d_in, const int* in_sizes, int n_in,
                              void* d_out, int out_size) {
    const float* x      = (const float*)d_in[0];
    const int*   ei     = (const int*)d_in[1];
    const int*   batch  = (const int*)d_in[2];
    const float* W1     = (const float*)d_in[3];
    const float* att_s1 = (const float*)d_in[4];
    const float* att_d1 = (const float*)d_in[5];
    const float* b1     = (const float*)d_in[6];
    const float* W2     = (const float*)d_in[7];
    const float* att_s2 = (const float*)d_in[8];
    const float* att_d2 = (const float*)d_in[9];
    const float* b2     = (const float*)d_in[10];
    const float* w_lin  = (const float*)d_in[11];
    const float* b_lin  = (const float*)d_in[12];
    float* out = (float*)d_out;

    cudaFuncSetAttribute(k_gemm_hist, cudaFuncAttributeMaxDynamicSharedMemorySize, SMEM_BYTES);

    const int WB = (N_NODES * 32 + 255) / 256;

    k_gemm_hist<<<GEMM_BLOCKS + HIST_TAIL, 256, SMEM_BYTES>>>(x, W1, att_s1, att_d1, ei);
    k_scan<<<SCAN_BLOCKS, 1024>>>();
    k_scatter<<<888, 256>>>(ei);
    k_aggregate<<<WB, 256>>>(b1);          // 4 <- profiled
    k_gemm_hist<<<GEMM_BLOCKS, 256, SMEM_BYTES>>>(nullptr, W2, att_s2, att_d2, nullptr);
    k_aggregate<<<WB, 256>>>(b2);
    k_pool<<<N_GRAPHS, 128>>>(batch, w_lin, b_lin, out);
}

// round 16
// speedup vs baseline: 1.2891x; 1.0305x over previous
#include <cuda_runtime.h>
#include <cuda_fp16.h>
#include <cstdint>

#define N_NODES 50000
#define N_EDGES 800000
#define ET (N_EDGES + N_NODES)
#define FDIM 128
#define HEADS 4
#define N_GRAPHS 64
#define OUT_CH 10
#define NEG 0.2f

#define GEMM_BLOCKS ((N_NODES + 127) / 128)        // 391
#define HIST_TAIL 148
#define SCAN_BLOCKS ((N_NODES + 1023) / 1024)      // 49

// fp16 GEMM smem: A[128][136] halves + B[128][136] halves + 256 floats att
#define AH 136
#define A_HALFS (128 * AH)
#define SMEM_BYTES (A_HALFS * 2 * 2 + 1024)        // 70656

// ---------------- scratch ----------------
__device__ __half2 g_h16[(size_t)N_NODES * FDIM / 2];   // GEMM output (gather source)
__device__ __half2 g_b16[(size_t)N_NODES * FDIM / 2];   // layer output (next GEMM input / pool)
__device__ float g_asrc[N_NODES * HEADS];
__device__ float g_adst[N_NODES * HEADS];
__device__ int   g_counts[N_NODES];                // zeroed by k_scan each run (and statically)
__device__ int   g_off[N_NODES + 1];
__device__ int   g_cur[N_NODES];
__device__ int   g_csrc[ET];
// decoupled-lookback state: (flag << 32) | value, flag: 0 invalid / 1 aggregate / 2 prefix.
__device__ __align__(8) unsigned long long g_state[SCAN_BLOCKS];

__device__ __forceinline__ float lrelu(float x) { return x > 0.f ? x : NEG * x; }
__device__ __forceinline__ uint32_t smem_u32(const void* p) {
    uint32_t a;
    asm("{ .reg .u64 t; cvta.to.shared.u64 t, %1; cvt.u32.u64 %0, t; }" : "=r"(a) : "l"(p));
    return a;
}
__device__ __forceinline__ void ldsm_x4(uint32_t* r, uint32_t addr) {
    asm volatile("ldmatrix.sync.aligned.m8n8.x4.shared.b16 {%0,%1,%2,%3}, [%4];"
        : "=r"(r[0]), "=r"(r[1]), "=r"(r[2]), "=r"(r[3]) : "r"(addr));
}
__device__ __forceinline__ void ldsm_x2t(uint32_t& r0, uint32_t& r1, uint32_t addr) {
    asm volatile("ldmatrix.sync.aligned.m8n8.x2.trans.shared.b16 {%0,%1}, [%2];"
        : "=r"(r0), "=r"(r1) : "r"(addr));
}
__device__ __forceinline__ void mma_f16(float* d, const uint32_t* a, uint32_t b0, uint32_t b1) {
    asm volatile(
        "mma.sync.aligned.m16n8k16.row.col.f32.f16.f16.f32 "
        "{%0,%1,%2,%3}, {%4,%5,%6,%7}, {%8,%9}, {%0,%1,%2,%3};"
        : "+f"(d[0]), "+f"(d[1]), "+f"(d[2]), "+f"(d[3])
        : "r"(a[0]), "r"(a[1]), "r"(a[2]), "r"(a[3]), "r"(b0), "r"(b1));
}
__device__ __forceinline__ uint32_t pack_h2(float a, float b) {
    __half2 h = __floats2half2_rn(a, b);
    return *(uint32_t*)&h;
}

// ---------------- fp16 tensor-core GEMM + fused attdot + (optional) hist tail ----------------
__global__ void __launch_bounds__(256, 2) k_gemm_hist(const float* __restrict__ Xext,
                                                      const float* __restrict__ W,
                                                      const float* __restrict__ att_s,
                                                      const float* __restrict__ att_d,
                                                      const int* __restrict__ ei) {
    if (blockIdx.x >= GEMM_BLOCKS) {
        if (ei) {
            const int4* dst4 = (const int4*)(ei + N_EDGES);
            for (int i = (blockIdx.x - GEMM_BLOCKS) * 256 + threadIdx.x; i < N_EDGES / 4;
                 i += HIST_TAIL * 256) {
                int4 d = dst4[i];
                atomicAdd(&g_counts[d.x], 1);
                atomicAdd(&g_counts[d.y], 1);
                atomicAdd(&g_counts[d.z], 1);
                atomicAdd(&g_counts[d.w], 1);
            }
        }
        return;
    }
    extern __shared__ __half smh[];
    __half* As = smh;                    // [128][136]
    __half* Bs = smh + A_HALFS;          // [128][136] k-major
    float* as_sm = (float*)(smh + 2 * A_HALFS);
    float* ad_sm = as_sm + 128;
    const int tid = threadIdx.x;
    const int wid = tid >> 5, lane = tid & 31;
    const int g = lane >> 2, t = lane & 3;
    const int wm = wid & 3, wn = wid >> 2;
    const int row0 = blockIdx.x * 128;

    if (tid < 128)      as_sm[tid] = att_s[tid];
    else                ad_sm[tid - 128] = att_d[tid - 128];

    if (Xext) {      // layer 1: fp32 input, convert
#pragma unroll
        for (int it = 0; it < 16; it++) {
            int idx = tid + it * 256;
            int r = idx >> 5, c4 = (idx & 31) * 4;
            int gr = row0 + r;
            uint2 pk = make_uint2(0u, 0u);
            if (gr < N_NODES) {
                float4 v = *(const float4*)&Xext[(size_t)gr * FDIM + c4];
                pk.x = pack_h2(v.x, v.y);
                pk.y = pack_h2(v.z, v.w);
            }
            *(uint2*)&As[r * AH + c4] = pk;
        }
    } else {         // layer 2: fp16 input, raw copy
#pragma unroll
        for (int it = 0; it < 16; it++) {
            int idx = tid + it * 256;
            int r = idx >> 5, c4 = (idx & 31) * 4;
            int gr = row0 + r;
            uint2 pk = make_uint2(0u, 0u);
            if (gr < N_NODES)
                pk = *(const uint2*)&g_b16[((size_t)gr * FDIM + c4) >> 1];
            *(uint2*)&As[r * AH + c4] = pk;
        }
    }
#pragma unroll
    for (int it = 0; it < 16; it++) {
        int idx = tid + it * 256;
        int k = idx >> 5, n4 = (idx & 31) * 4;
        float4 v = *(const float4*)&W[(size_t)k * FDIM + n4];
        uint2 pk;
        pk.x = pack_h2(v.x, v.y);
        pk.y = pack_h2(v.z, v.w);
        *(uint2*)&Bs[k * AH + n4] = pk;
    }
    __syncthreads();

    const uint32_t sbase = smem_u32(smh);
    const int lrow = (lane & 7) + ((lane >> 3) & 1) * 8;
    const int khi  = ((lane >> 4) & 1) * 8;
    uint32_t aaddr0 = sbase + (uint32_t)(((wm * 32 + 0)  + lrow) * AH + khi) * 2;
    uint32_t aaddr1 = sbase + (uint32_t)(((wm * 32 + 16) + lrow) * AH + khi) * 2;
    uint32_t baddr  = sbase + (uint32_t)(A_HALFS + (lane & 15) * AH + wn * 64) * 2;

    float d[2][8][4];
#pragma unroll
    for (int mi = 0; mi < 2; mi++)
#pragma unroll
        for (int ni = 0; ni < 8; ni++)
#pragma unroll
            for (int k = 0; k < 4; k++) d[mi][ni][k] = 0.f;

#pragma unroll
    for (int ks = 0; ks < 8; ks++) {
        uint32_t a[2][4];
        ldsm_x4(a[0], aaddr0 + ks * 32);
        ldsm_x4(a[1], aaddr1 + ks * 32);
        uint32_t bk = baddr + (uint32_t)(ks * 16 * AH) * 2;
#pragma unroll
        for (int ni = 0; ni < 8; ni++) {
            uint32_t b0, b1;
            ldsm_x2t(b0, b1, bk + ni * 16);
            mma_f16(d[0][ni], a[0], b0, b1);
            mma_f16(d[1][ni], a[1], b0, b1);
        }
    }

    const int h0 = 2 * wn;
#pragma unroll
    for (int mi = 0; mi < 2; mi++) {
        int r0 = row0 + wm * 32 + mi * 16 + g;
        int r1 = r0 + 8;
        float s0a = 0.f, s0b = 0.f, d0a = 0.f, d0b = 0.f;
        float s1a = 0.f, s1b = 0.f, d1a = 0.f, d1b = 0.f;
#pragma unroll
        for (int ni = 0; ni < 8; ni++) {
            int col = wn * 64 + ni * 8 + t * 2;
            float w0s = as_sm[col], w1s = as_sm[col + 1];
            float w0d = ad_sm[col], w1d = ad_sm[col + 1];
            float v00 = d[mi][ni][0], v01 = d[mi][ni][1];
            float v10 = d[mi][ni][2], v11 = d[mi][ni][3];
            if (r0 < N_NODES) *(uint32_t*)&g_h16[((size_t)r0 * FDIM + col) >> 1] = pack_h2(v00, v01);
            if (r1 < N_NODES) *(uint32_t*)&g_h16[((size_t)r1 * FDIM + col) >> 1] = pack_h2(v10, v11);
            if (ni < 4) {
                s0a = fmaf(v00, w0s, fmaf(v01, w1s, s0a));
                d0a = fmaf(v00, w0d, fmaf(v01, w1d, d0a));
                s1a = fmaf(v10, w0s, fmaf(v11, w1s, s1a));
                d1a = fmaf(v10, w0d, fmaf(v11, w1d, d1a));
            } else {
                s0b = fmaf(v00, w0s, fmaf(v01, w1s, s0b));
                d0b = fmaf(v00, w0d, fmaf(v01, w1d, d0b));
                s1b = fmaf(v10, w0s, fmaf(v11, w1s, s1b));
                d1b = fmaf(v10, w0d, fmaf(v11, w1d, d1b));
            }
        }
#pragma unroll
        for (int o = 1; o <= 2; o <<= 1) {
            s0a += __shfl_down_sync(0xffffffffu, s0a, o);
            s0b += __shfl_down_sync(0xffffffffu, s0b, o);
            d0a += __shfl_down_sync(0xffffffffu, d0a, o);
            d0b += __shfl_down_sync(0xffffffffu, d0b, o);
            s1a += __shfl_down_sync(0xffffffffu, s1a, o);
            s1b += __shfl_down_sync(0xffffffffu, s1b, o);
            d1a += __shfl_down_sync(0xffffffffu, d1a, o);
            d1b += __shfl_down_sync(0xffffffffu, d1b, o);
        }
        if (t == 0) {
            if (r0 < N_NODES) {
                g_asrc[r0 * HEADS + h0] = s0a; g_asrc[r0 * HEADS + h0 + 1] = s0b;
                g_adst[r0 * HEADS + h0] = d0a; g_adst[r0 * HEADS + h0 + 1] = d0b;
            }
            if (r1 < N_NODES) {
                g_asrc[r1 * HEADS + h0] = s1a; g_asrc[r1 * HEADS + h0 + 1] = s1b;
                g_adst[r1 * HEADS + h0] = d1a; g_adst[r1 * HEADS + h0 + 1] = d1b;
            }
        }
    }
}

// ---------------- single-kernel decoupled-lookback scan (packed-word protocol) ----------------
__global__ void __launch_bounds__(1024) k_scan() {
    __shared__ int sh[1024];
    __shared__ int s_base;
    const int bid = blockIdx.x, tid = threadIdx.x;
    const int i = bid * 1024 + tid;
    int v = 0;
    if (i < N_NODES) {
        v = g_counts[i] + 1;       // +1 self loop
        g_counts[i] = 0;           // reset for next replay
    }
    sh[tid] = v;
    __syncthreads();
#pragma unroll
    for (int off = 1; off < 1024; off <<= 1) {
        int t = (tid >= off) ? sh[tid - off] : 0;
        __syncthreads();
        sh[tid] += t;
        __syncthreads();
    }
    const int total = sh[1023];

    if (tid == 0) {
        volatile unsigned long long* st = (volatile unsigned long long*)g_state;
        if (bid == 0) {
            st[0] = (2ull << 32) | (unsigned)total;
            s_base = 0;
        } else {
            st[bid] = (1ull << 32) | (unsigned)total;
            int run = 0;
            int j = bid - 1;
            while (true) {
                unsigned long long s = st[j];
                unsigned f = (unsigned)(s >> 32);
                if (f == 2u) { run += (int)(unsigned)s; break; }
                if (f == 1u) { run += (int)(unsigned)s; j--; }
            }
            st[bid] = (2ull << 32) | (unsigned)(run + total);
            s_base = run;
        }
    }
    __syncthreads();
    const int base = s_base;
    if (i < N_NODES) {
        int o = base + sh[tid] - v;
        g_off[i] = o;
        g_csrc[o] = i;                // self loop in slot 0
        g_cur[i] = o + 1;
        if (i == N_NODES - 1) g_off[N_NODES] = o + v;
    }
}

// ---------------- CSR scatter (real edges only) + lookback-state reset ----------------
__global__ void k_scatter(const int* __restrict__ ei) {
    int gi = blockIdx.x * blockDim.x + threadIdx.x;
    if (gi < SCAN_BLOCKS) g_state[gi] = 0ull;
    for (int i = gi; i < N_EDGES; i += gridDim.x * blockDim.x) {
        int s = ei[i], d = ei[N_EDGES + i];
        int pos = atomicAdd(&g_cur[d], 1);
        g_csrc[pos] = s;
    }
}

// ---------------- warp-cooperative, pipelined softmax aggregation (32-bit addressing) ----------------
__global__ void __launch_bounds__(256, 6) k_aggregate(const float* __restrict__ bias) {
    int d = (blockIdx.x * 256 + threadIdx.x) >> 5;
    int lane = threadIdx.x & 31;
    if (d >= N_NODES) return;
    const int beg = g_off[d], end = g_off[d + 1];
    const int myh = lane >> 3;
    const int u_of = lane & 7;
    const int ch = lane * 4;
    const int chB = lane * 8;              // byte offset of this lane's 4 halves within a 256B row
    const float adm = g_adst[d * HEADS + myh];
    const float* __restrict__ asr = (const float*)g_asrc;
    const char* __restrict__ hb = (const char*)g_h16;
    const int wsrc = (lane & 24);

    float4 acc0 = make_float4(0.f, 0.f, 0.f, 0.f);
    float4 acc1 = make_float4(0.f, 0.f, 0.f, 0.f);
    float den = 0.f;
    const int last = end - 1;

    // prologue: load batch 0's (edge,head) score
    int jj0 = beg + u_of;
    int  sOwn = g_csrc[jj0 < end ? jj0 : last];
    float aOwn = asr[sOwn * HEADS + myh];
    bool  vOwn = jj0 < end;

    for (int j = beg; j < end; j += 8) {
        float wOwn = vOwn ? __expf(lrelu(aOwn + adm)) : 0.f;

        int oU[8];
        float wU[8];
#pragma unroll
        for (int u = 0; u < 8; u++) {
            oU[u] = (__shfl_sync(0xffffffffu, sOwn, u) << 8) + chB;   // 32-bit byte offset
            wU[u] = __shfl_sync(0xffffffffu, wOwn, wsrc | u);
        }

        // prefetch next batch's own score (overlaps with h gather + math below)
        int jn = j + 8;
        if (jn < end) {
            int jj = jn + u_of;
            vOwn = jj < end;
            sOwn = g_csrc[jj < end ? jj : last];
            aOwn = asr[sOwn * HEADS + myh];
        }

        uint2 hr[8];
#pragma unroll
        for (int u = 0; u < 8; u++)
            hr[u] = *(const uint2*)(hb + oU[u]);
#pragma unroll
        for (int u = 0; u < 8; u += 2) {
            float2 p0 = __half22float2(*(__half2*)&hr[u].x);
            float2 p1 = __half22float2(*(__half2*)&hr[u].y);
            float2 q0 = __half22float2(*(__half2*)&hr[u + 1].x);
            float2 q1 = __half22float2(*(__half2*)&hr[u + 1].y);
            den += wU[u] + wU[u + 1];
            acc0.x = fmaf(wU[u], p0.x, acc0.x);     acc0.y = fmaf(wU[u], p0.y, acc0.y);
            acc0.z = fmaf(wU[u], p1.x, acc0.z);     acc0.w = fmaf(wU[u], p1.y, acc0.w);
            acc1.x = fmaf(wU[u + 1], q0.x, acc1.x); acc1.y = fmaf(wU[u + 1], q0.y, acc1.y);
            acc1.z = fmaf(wU[u + 1], q1.x, acc1.z); acc1.w = fmaf(wU[u + 1], q1.y, acc1.w);
        }
    }
    const float inv = 1.f / den;
    float4 b = *(const float4*)&bias[ch];
    float rx = fmaxf(fmaf(acc0.x + acc1.x, inv, b.x), 0.f);
    float ry = fmaxf(fmaf(acc0.y + acc1.y, inv, b.y), 0.f);
    float rz = fmaxf(fmaf(acc0.z + acc1.z, inv, b.z), 0.f);
    float rw = fmaxf(fmaf(acc0.w + acc1.w, inv, b.w), 0.f);
    uint2 outp;
    outp.x = pack_h2(rx, ry);
    outp.y = pack_h2(rz, rw);
    *(uint2*)&g_b16[((size_t)d * FDIM + ch) >> 1] = outp;
}

// ---------------- global mean pool + linear head (fp16 input) ----------------
__global__ void k_pool(const int* __restrict__ batch,
                       const float* __restrict__ w_lin,
                       const float* __restrict__ b_lin,
                       float* __restrict__ out) {
    int g = blockIdx.x;
    __shared__ int s_lo, s_hi;
    __shared__ float pooled[FDIM];
    if (threadIdx.x == 0) {
        int lo = 0, hi = N_NODES;
        while (lo < hi) { int mid = (lo + hi) >> 1; if (batch[mid] < g) lo = mid + 1; else hi = mid; }
        s_lo = lo;
        hi = N_NODES;
        while (lo < hi) { int mid = (lo + hi) >> 1; if (batch[mid] < g + 1) lo = mid + 1; else hi = mid; }
        s_hi = lo;
    }
    __syncthreads();
    int lo = s_lo, hi = s_hi;
    const __half* hb = (const __half*)g_b16;
    float a0 = 0.f, a1 = 0.f, a2 = 0.f, a3 = 0.f;
    int n = lo;
    for (; n + 4 <= hi; n += 4) {
        a0 += __half2float(hb[(size_t)(n + 0) * FDIM + threadIdx.x]);
        a1 += __half2float(hb[(size_t)(n + 1) * FDIM + threadIdx.x]);
        a2 += __half2float(hb[(size_t)(n + 2) * FDIM + threadIdx.x]);
        a3 += __half2float(hb[(size_t)(n + 3) * FDIM + threadIdx.x]);
    }
    for (; n < hi; n++) a0 += __half2float(hb[(size_t)n * FDIM + threadIdx.x]);
    float cnt = (float)(hi - lo);
    pooled[threadIdx.x] = (a0 + a1 + a2 + a3) / fmaxf(cnt, 1.f);
    __syncthreads();
    if (threadIdx.x < OUT_CH) {
        float acc = b_lin[threadIdx.x];
        for (int c = 0; c < FDIM; c++) acc += pooled[c] * w_lin[c * OUT_CH + threadIdx.x];
        out[g * OUT_CH + threadIdx.x] = acc;
    }
}

// ---------------- launch (7 kernels) ----------------
extern "C" void kernel_launch(void* const* d_in, const int* in_sizes, int n_in,
                              void* d_out, int out_size) {
    const float* x      = (const float*)d_in[0];
    const int*   ei     = (const int*)d_in[1];
    const int*   batch  = (const int*)d_in[2];
    const float* W1     = (const float*)d_in[3];
    const float* att_s1 = (const float*)d_in[4];
    const float* att_d1 = (const float*)d_in[5];
    const float* b1     = (const float*)d_in[6];
    const float* W2     = (const float*)d_in[7];
    const float* att_s2 = (const float*)d_in[8];
    const float* att_d2 = (const float*)d_in[9];
    const float* b2     = (const float*)d_in[10];
    const float* w_lin  = (const float*)d_in[11];
    const float* b_lin  = (const float*)d_in[12];
    float* out = (float*)d_out;

    cudaFuncSetAttribute(k_gemm_hist, cudaFuncAttributeMaxDynamicSharedMemorySize, SMEM_BYTES);

    const int WB = (N_NODES * 32 + 255) / 256;

    k_gemm_hist<<<GEMM_BLOCKS + HIST_TAIL, 256, SMEM_BYTES>>>(x, W1, att_s1, att_d1, ei);
    k_scan<<<SCAN_BLOCKS, 1024>>>();
    k_scatter<<<888, 256>>>(ei);
    k_aggregate<<<WB, 256>>>(b1);          // 4 <- profiled
    k_gemm_hist<<<GEMM_BLOCKS, 256, SMEM_BYTES>>>(nullptr, W2, att_s2, att_d2, nullptr);
    k_aggregate<<<WB, 256>>>(b2);
    k_pool<<<N_GRAPHS, 128>>>(batch, w_lin, b_lin, out);
}